// round 1
// baseline (speedup 1.0000x reference)
#include <cuda_runtime.h>

#define HID     256
#define NNODES  100000
#define NEDGES  400000
#define NGRAPHS 256
#define NLAYERS 3
#define BIO     512

// ---------------- scratch (device globals; no allocation allowed) ----------------
__device__ float g_e[(size_t)NEDGES * HID];   // edge features (409.6 MB)
__device__ float g_t[(size_t)NEDGES * HID];   // MLP temp (also reused for node temp)
__device__ float g_h[(size_t)NNODES * HID];   // node features
__device__ float g_z[(size_t)NNODES * HID];   // aggregation buffer
__device__ float g_amean[NGRAPHS * HID];      // alpha * mean per (graph, channel)
__device__ float g_rstd[NGRAPHS * HID];       // rsqrt(var + eps)
__device__ float g_pool[NGRAPHS * HID];       // final mean pool
__device__ float g_cbio[HID];                 // bio @ head_W1[256:,:] (graph-independent)
__device__ int   g_cnt[NGRAPHS];
__device__ int   g_start[NGRAPHS];

// ---------------- elementwise kernels ----------------
__global__ void k_node_emb(const int* __restrict__ x, const float* __restrict__ W) {
    int i = blockIdx.x * blockDim.x + threadIdx.x;
    if (i >= NNODES * HID) return;
    int n = i >> 8, c = i & 255;
    g_h[i] = W[x[n] * HID + c];
}

__global__ void k_edge_emb(const float* __restrict__ ea, const float* __restrict__ W,
                           const float* __restrict__ b) {
    int i = blockIdx.x * blockDim.x + threadIdx.x;
    if (i >= NEDGES * HID) return;
    int e = i >> 8, c = i & 255;
    const float* a = ea + e * 4;
    g_e[i] = b[c] + a[0] * W[c] + a[1] * W[HID + c] + a[2] * W[2 * HID + c] + a[3] * W[3 * HID + c];
}

__global__ void k_zinit(const float* __restrict__ eps, int l) {
    int i = blockIdx.x * blockDim.x + threadIdx.x;
    if (i >= NNODES * HID) return;
    g_z[i] = (1.f + eps[l]) * g_h[i];
}

__global__ void k_scatter(const int* __restrict__ src, const int* __restrict__ dst) {
    int i = blockIdx.x * blockDim.x + threadIdx.x;
    if (i >= NEDGES * HID) return;
    int e = i >> 8, c = i & 255;
    float v = g_h[src[e] * HID + c] + g_e[i];
    v = fmaxf(v, 0.f);
    atomicAdd(&g_z[dst[e] * HID + c], v);
}

// ---------------- per-graph bookkeeping (batch is sorted) ----------------
__global__ void k_zero_cnt() { g_cnt[threadIdx.x] = 0; }

__global__ void k_count(const int* __restrict__ batch) {
    int i = blockIdx.x * blockDim.x + threadIdx.x;
    if (i < NNODES) atomicAdd(&g_cnt[batch[i]], 1);
}

__global__ void k_scan() {
    if (threadIdx.x == 0) {
        int acc = 0;
        for (int g = 0; g < NGRAPHS; g++) { g_start[g] = acc; acc += g_cnt[g]; }
    }
}

// alpha != nullptr : GraphNorm stats (amean, rstd); alpha == nullptr : mean pool
__global__ void k_stats(const float* __restrict__ alpha) {
    int g = blockIdx.x, c = threadIdx.x;
    int s = g_start[g], n = g_cnt[g];
    float sum = 0.f, sq = 0.f;
    #pragma unroll 4
    for (int i = 0; i < n; i++) {
        float v = g_h[(size_t)(s + i) * HID + c];
        sum += v; sq += v * v;
    }
    float inv = 1.f / (float)(n > 0 ? n : 1);
    float mu = sum * inv;
    if (alpha) {
        float al = alpha[c];
        float var = sq * inv - (2.f * al - al * al) * mu * mu;
        g_amean[g * HID + c] = al * mu;
        g_rstd[g * HID + c]  = rsqrtf(var + 1e-5f);
    } else {
        g_pool[g * HID + c] = mu;
    }
}

__global__ void k_norm(const int* __restrict__ batch, const float* __restrict__ gamma,
                       const float* __restrict__ beta) {
    int i = blockIdx.x * blockDim.x + threadIdx.x;
    if (i >= NNODES * HID) return;
    int nidx = i >> 8, c = i & 255;
    int g = batch[nidx];
    float v = (g_h[i] - g_amean[g * HID + c]) * g_rstd[g * HID + c];
    g_h[i] = gamma[c] * v + beta[c];
}

// ---------------- fp32 tiled GEMM: C[M,256] = act(A[M,256] @ W[256,256] + bias) ----------------
// RELU: apply relu; SCALE: multiply row by struct_scale if edge_attr[row*4+1] > 0
template <int RELU, int SCALE>
__global__ void k_gemm(const float* __restrict__ A, const float* __restrict__ W,
                       const float* __restrict__ bias, float* __restrict__ C, int M,
                       const float* __restrict__ eattr, const float* __restrict__ ss) {
    __shared__ float As[64][16];
    __shared__ float Bs[16][64];
    int bm = blockIdx.y * 64, bn = blockIdx.x * 64;
    int tid = threadIdx.x;
    int tx = tid & 15, ty = tid >> 4;
    float acc[4][4] = {};

    for (int k0 = 0; k0 < HID; k0 += 16) {
        #pragma unroll
        for (int i = 0; i < 4; i++) {
            int idx = tid + i * 256;
            int m = idx >> 4, k = idx & 15;
            int gm = bm + m;
            As[m][k] = (gm < M) ? A[(size_t)gm * HID + k0 + k] : 0.f;
            int kk = idx >> 6, n = idx & 63;
            Bs[kk][n] = W[(k0 + kk) * HID + bn + n];
        }
        __syncthreads();
        #pragma unroll
        for (int k = 0; k < 16; k++) {
            float a0 = As[ty * 4 + 0][k];
            float a1 = As[ty * 4 + 1][k];
            float a2 = As[ty * 4 + 2][k];
            float a3 = As[ty * 4 + 3][k];
            float4 bv = *(const float4*)&Bs[k][tx * 4];
            acc[0][0] += a0 * bv.x; acc[0][1] += a0 * bv.y; acc[0][2] += a0 * bv.z; acc[0][3] += a0 * bv.w;
            acc[1][0] += a1 * bv.x; acc[1][1] += a1 * bv.y; acc[1][2] += a1 * bv.z; acc[1][3] += a1 * bv.w;
            acc[2][0] += a2 * bv.x; acc[2][1] += a2 * bv.y; acc[2][2] += a2 * bv.z; acc[2][3] += a2 * bv.w;
            acc[3][0] += a3 * bv.x; acc[3][1] += a3 * bv.y; acc[3][2] += a3 * bv.z; acc[3][3] += a3 * bv.w;
        }
        __syncthreads();
    }

    #pragma unroll
    for (int i = 0; i < 4; i++) {
        int gm = bm + ty * 4 + i;
        if (gm >= M) continue;
        float rs = 1.f;
        if (SCALE) rs = (eattr[(size_t)gm * 4 + 1] > 0.f) ? ss[0] : 1.f;
        #pragma unroll
        for (int j = 0; j < 4; j++) {
            int gn = bn + tx * 4 + j;
            float v = acc[i][j] + bias[gn];
            if (RELU) v = fmaxf(v, 0.f);
            C[(size_t)gm * HID + gn] = rs * v;
        }
    }
}

// ---------------- head ----------------
__global__ void k_cbio(const float* __restrict__ bio, const float* __restrict__ W1) {
    int j = threadIdx.x;  // 1 block, 256 threads
    float acc = 0.f;
    for (int k = 0; k < BIO; k++) acc += bio[k] * W1[(HID + k) * HID + j];
    g_cbio[j] = acc;
}

__global__ void k_head(const float* __restrict__ W1, const float* __restrict__ b1,
                       const float* __restrict__ W2, const float* __restrict__ b2,
                       float* __restrict__ out) {
    int g = blockIdx.x, j = threadIdx.x;
    __shared__ float sh[HID];
    __shared__ float red[HID];
    sh[j] = g_pool[g * HID + j];
    __syncthreads();
    float acc = b1[j] + g_cbio[j];
    for (int k = 0; k < HID; k++) acc += sh[k] * W1[k * HID + j];
    acc = fmaxf(acc, 0.f);
    red[j] = acc * W2[j];
    __syncthreads();
    for (int st = 128; st > 0; st >>= 1) {
        if (j < st) red[j] += red[j + st];
        __syncthreads();
    }
    if (j == 0) out[g] = red[0] + b2[0];
}

// ---------------- launch ----------------
extern "C" void kernel_launch(void* const* d_in, const int* in_sizes, int n_in,
                              void* d_out, int out_size) {
    const int*   x    = (const int*)d_in[0];
    const int*   ei   = (const int*)d_in[1];
    const float* ea   = (const float*)d_in[2];
    const int*   batch= (const int*)d_in[3];
    const float* nodeW= (const float*)d_in[4];
    const float* eW   = (const float*)d_in[5];
    const float* eb   = (const float*)d_in[6];
    const float* mW1  = (const float*)d_in[7];
    const float* mb1  = (const float*)d_in[8];
    const float* mW2  = (const float*)d_in[9];
    const float* mb2  = (const float*)d_in[10];
    const float* ss   = (const float*)d_in[11];
    const float* cW1  = (const float*)d_in[12];
    const float* cb1  = (const float*)d_in[13];
    const float* cW2  = (const float*)d_in[14];
    const float* cb2  = (const float*)d_in[15];
    const float* ceps = (const float*)d_in[16];
    const float* ng   = (const float*)d_in[17];
    const float* nb   = (const float*)d_in[18];
    const float* na   = (const float*)d_in[19];
    const float* bio  = (const float*)d_in[20];
    const float* hW1  = (const float*)d_in[21];
    const float* hb1  = (const float*)d_in[22];
    const float* hW2  = (const float*)d_in[23];
    const float* hb2  = (const float*)d_in[24];
    float* out = (float*)d_out;

    const int* src = ei;
    const int* dst = ei + NEDGES;

    void *pe, *pt, *ph, *pz;
    cudaGetSymbolAddress(&pe, g_e);
    cudaGetSymbolAddress(&pt, g_t);
    cudaGetSymbolAddress(&ph, g_h);
    cudaGetSymbolAddress(&pz, g_z);
    float* fe = (float*)pe;
    float* ft = (float*)pt;
    float* fh = (float*)ph;
    float* fz = (float*)pz;

    const int T = 256;
    int nodeElems = NNODES * HID;
    int edgeElems = NEDGES * HID;

    // node + edge embeddings
    k_node_emb<<<(nodeElems + T - 1) / T, T>>>(x, nodeW);
    k_edge_emb<<<(edgeElems + T - 1) / T, T>>>(ea, eW, eb);

    // edge MLP: t = relu(e @ W1 + b1); e = (t @ W2 + b2) * struct_scale(row)
    dim3 ge(HID / 64, (NEDGES + 63) / 64);
    k_gemm<1, 0><<<ge, 256>>>(fe, mW1, mb1, ft, NEDGES, nullptr, nullptr);
    k_gemm<0, 1><<<ge, 256>>>(ft, mW2, mb2, fe, NEDGES, ea, ss);

    // per-graph ranges (batch sorted)
    k_zero_cnt<<<1, NGRAPHS>>>();
    k_count<<<(NNODES + T - 1) / T, T>>>(batch);
    k_scan<<<1, 32>>>();

    dim3 gn(HID / 64, (NNODES + 63) / 64);
    for (int l = 0; l < NLAYERS; l++) {
        k_zinit<<<(nodeElems + T - 1) / T, T>>>(ceps, l);
        k_scatter<<<(edgeElems + T - 1) / T, T>>>(src, dst);
        k_gemm<1, 0><<<gn, 256>>>(fz, cW1 + l * HID * HID, cb1 + l * HID, ft, NNODES, nullptr, nullptr);
        k_gemm<0, 0><<<gn, 256>>>(ft, cW2 + l * HID * HID, cb2 + l * HID, fh, NNODES, nullptr, nullptr);
        k_stats<<<NGRAPHS, HID>>>(na + l * HID);
        k_norm<<<(nodeElems + T - 1) / T, T>>>(batch, ng + l * HID, nb + l * HID);
    }

    // pool + head
    k_stats<<<NGRAPHS, HID>>>(nullptr);
    k_cbio<<<1, HID>>>(bio, hW1);
    k_head<<<NGRAPHS, HID>>>(hW1, hb1, hW2, hb2, out);
}

// round 3
// speedup vs baseline: 1.4903x; 1.4903x over previous
#include <cuda_runtime.h>
#include <cuda_bf16.h>
#include <cstdint>

#define HID     256
#define NNODES  100000
#define NEDGES  400000
#define NGRAPHS 256
#define NLAYERS 3
#define BIO     512

// ---------------- scratch (device globals; no allocation allowed) ----------------
__device__ float g_e[(size_t)NEDGES * HID];
__device__ float g_t[(size_t)NEDGES * HID];
__device__ float g_h[(size_t)NNODES * HID];
__device__ float g_z[(size_t)NNODES * HID];
__device__ float g_amean[NGRAPHS * HID];
__device__ float g_rstd[NGRAPHS * HID];
__device__ float g_pool[NGRAPHS * HID];
__device__ float g_cbio[HID];
__device__ int   g_cnt[NGRAPHS];
__device__ int   g_start[NGRAPHS];
// pre-transposed + split weights: 8 matrices of [N=256][K=256] bf16
__device__ __nv_bfloat16 g_wt_hi[8 * 65536];
__device__ __nv_bfloat16 g_wt_lo[8 * 65536];

// ---------------- helpers ----------------
__device__ __forceinline__ uint32_t smem_u32(const void* p) {
    uint32_t a;
    asm("{ .reg .u64 t; cvta.to.shared.u64 t, %1; cvt.u32.u64 %0, t; }" : "=r"(a) : "l"(p));
    return a;
}
__device__ __forceinline__ uint32_t lds32(uint32_t addr) {
    uint32_t v;
    asm volatile("ld.shared.b32 %0, [%1];" : "=r"(v) : "r"(addr));
    return v;
}
__device__ __forceinline__ void mma_bf16(float* d, const uint32_t* a, uint32_t b0, uint32_t b1) {
    asm volatile(
        "mma.sync.aligned.m16n8k16.row.col.f32.bf16.bf16.f32 "
        "{%0,%1,%2,%3}, {%4,%5,%6,%7}, {%8,%9}, {%0,%1,%2,%3};"
        : "+f"(d[0]), "+f"(d[1]), "+f"(d[2]), "+f"(d[3])
        : "r"(a[0]), "r"(a[1]), "r"(a[2]), "r"(a[3]), "r"(b0), "r"(b1));
}

// ---------------- HMMA GEMM: C[M,256] = act(A[M,256] @ W + b), W pre-split [n][k] ----------------
// CTA: 128(M) x 128(N); 8 warps 4x2, warp tile 32x64.
// Split precision: D += ah*bh + ah*bl + al*bh.
#define LDB 40  // bf16 elements per smem row (32 data + 8 pad); 80 bytes
template <int RELU, int SCALE>
__global__ __launch_bounds__(256) void k_mgemm(
    const float* __restrict__ A, const __nv_bfloat16* __restrict__ Bhi,
    const __nv_bfloat16* __restrict__ Blo, const float* __restrict__ bias,
    float* __restrict__ C, int M, const float* __restrict__ eattr,
    const float* __restrict__ ss) {
    __shared__ __nv_bfloat16 sAhi[128 * LDB];
    __shared__ __nv_bfloat16 sAlo[128 * LDB];
    __shared__ __nv_bfloat16 sBhi[128 * LDB];
    __shared__ __nv_bfloat16 sBlo[128 * LDB];

    const uint32_t AHI = smem_u32(sAhi), ALO = smem_u32(sAlo);
    const uint32_t BHI = smem_u32(sBhi), BLO = smem_u32(sBlo);

    int tid = threadIdx.x, lane = tid & 31, wid = tid >> 5;
    int warpm = wid & 3, warpn = wid >> 2;          // 4 x 2
    int tile_m = blockIdx.x * 128, bn = blockIdx.y * 128;

    float acc[2][8][4];
    #pragma unroll
    for (int m = 0; m < 2; m++)
        #pragma unroll
        for (int n = 0; n < 8; n++)
            #pragma unroll
            for (int j = 0; j < 4; j++) acc[m][n][j] = 0.f;

    int qgrp = lane >> 2, qidx = lane & 3;           // lane/4, lane%4

    for (int kc = 0; kc < 8; kc++) {
        int k0 = kc * 32;
        // ---- load A chunk [128 x 32] fp32 -> split hi/lo bf16 into smem ----
        #pragma unroll
        for (int i = 0; i < 4; i++) {
            int idx = tid + i * 256;                 // < 1024
            int row = idx >> 3, f4 = idx & 7;
            float4 v = make_float4(0.f, 0.f, 0.f, 0.f);
            int gr = tile_m + row;
            if (gr < M) v = *(const float4*)(A + (size_t)gr * HID + k0 + f4 * 4);
            __nv_bfloat162 h01 = __floats2bfloat162_rn(v.x, v.y);
            __nv_bfloat162 h23 = __floats2bfloat162_rn(v.z, v.w);
            __nv_bfloat162 l01 = __floats2bfloat162_rn(v.x - __low2float(h01), v.y - __high2float(h01));
            __nv_bfloat162 l23 = __floats2bfloat162_rn(v.z - __low2float(h23), v.w - __high2float(h23));
            uint32_t off = row * (LDB * 2) + f4 * 8;
            uint32_t u0 = reinterpret_cast<uint32_t&>(h01), u1 = reinterpret_cast<uint32_t&>(h23);
            uint32_t u2 = reinterpret_cast<uint32_t&>(l01), u3 = reinterpret_cast<uint32_t&>(l23);
            asm volatile("st.shared.v2.b32 [%0], {%1,%2};" :: "r"(AHI + off), "r"(u0), "r"(u1));
            asm volatile("st.shared.v2.b32 [%0], {%1,%2};" :: "r"(ALO + off), "r"(u2), "r"(u3));
        }
        // ---- load B chunk [128(n) x 32(k)] bf16 hi/lo into smem ----
        #pragma unroll
        for (int i = 0; i < 2; i++) {
            int idx = tid + i * 256;                 // < 512
            int row = idx >> 2, q = idx & 3;
            uint4 vh = *(const uint4*)(Bhi + (size_t)(bn + row) * HID + k0 + q * 8);
            uint4 vl = *(const uint4*)(Blo + (size_t)(bn + row) * HID + k0 + q * 8);
            uint32_t off = row * (LDB * 2) + q * 16;
            asm volatile("st.shared.v4.b32 [%0], {%1,%2,%3,%4};"
                         :: "r"(BHI + off), "r"(vh.x), "r"(vh.y), "r"(vh.z), "r"(vh.w));
            asm volatile("st.shared.v4.b32 [%0], {%1,%2,%3,%4};"
                         :: "r"(BLO + off), "r"(vl.x), "r"(vl.y), "r"(vl.z), "r"(vl.w));
        }
        __syncthreads();

        #pragma unroll
        for (int ks = 0; ks < 2; ks++) {
            int kb = ks * 16;
            uint32_t ah[2][4], al[2][4];
            #pragma unroll
            for (int m = 0; m < 2; m++) {
                int r0 = warpm * 32 + m * 16 + qgrp;
                uint32_t o00 = r0 * (LDB * 2) + kb * 2 + qidx * 4;
                uint32_t o10 = o00 + 8 * (LDB * 2);
                ah[m][0] = lds32(AHI + o00); ah[m][1] = lds32(AHI + o10);
                ah[m][2] = lds32(AHI + o00 + 16); ah[m][3] = lds32(AHI + o10 + 16);
                al[m][0] = lds32(ALO + o00); al[m][1] = lds32(ALO + o10);
                al[m][2] = lds32(ALO + o00 + 16); al[m][3] = lds32(ALO + o10 + 16);
            }
            #pragma unroll
            for (int n = 0; n < 8; n++) {
                int col = warpn * 64 + n * 8 + qgrp;
                uint32_t ob = col * (LDB * 2) + kb * 2 + qidx * 4;
                uint32_t bh0 = lds32(BHI + ob), bh1 = lds32(BHI + ob + 16);
                uint32_t bl0 = lds32(BLO + ob), bl1 = lds32(BLO + ob + 16);
                #pragma unroll
                for (int m = 0; m < 2; m++) {
                    mma_bf16(acc[m][n], ah[m], bh0, bh1);
                    mma_bf16(acc[m][n], ah[m], bl0, bl1);
                    mma_bf16(acc[m][n], al[m], bh0, bh1);
                }
            }
        }
        __syncthreads();
    }

    // ---- epilogue ----
    #pragma unroll
    for (int m = 0; m < 2; m++) {
        int r0 = tile_m + warpm * 32 + m * 16 + qgrp;
        int r1 = r0 + 8;
        float rs0 = 1.f, rs1 = 1.f;
        if (SCALE) {
            if (r0 < M) rs0 = (eattr[(size_t)r0 * 4 + 1] > 0.f) ? ss[0] : 1.f;
            if (r1 < M) rs1 = (eattr[(size_t)r1 * 4 + 1] > 0.f) ? ss[0] : 1.f;
        }
        #pragma unroll
        for (int n = 0; n < 8; n++) {
            int col = bn + warpn * 64 + n * 8 + qidx * 2;
            float b0 = __ldg(bias + col), b1 = __ldg(bias + col + 1);
            float v0 = acc[m][n][0] + b0, v1 = acc[m][n][1] + b1;
            float v2 = acc[m][n][2] + b0, v3 = acc[m][n][3] + b1;
            if (RELU) {
                v0 = fmaxf(v0, 0.f); v1 = fmaxf(v1, 0.f);
                v2 = fmaxf(v2, 0.f); v3 = fmaxf(v3, 0.f);
            }
            if (r0 < M) *(float2*)(C + (size_t)r0 * HID + col) = make_float2(v0 * rs0, v1 * rs0);
            if (r1 < M) *(float2*)(C + (size_t)r1 * HID + col) = make_float2(v2 * rs1, v3 * rs1);
        }
    }
}

// ---------------- weight transpose + split: Wt[n][k] = split(W[k][n]) ----------------
__global__ void k_wsplit(const float* __restrict__ W, int slot) {
    int k = blockIdx.x, n = threadIdx.x;
    float v = W[k * HID + n];
    __nv_bfloat16 hi = __float2bfloat16(v);
    __nv_bfloat16 lo = __float2bfloat16(v - __bfloat162float(hi));
    g_wt_hi[(size_t)slot * 65536 + n * HID + k] = hi;
    g_wt_lo[(size_t)slot * 65536 + n * HID + k] = lo;
}

// ---------------- elementwise kernels ----------------
__global__ void k_node_emb(const int* __restrict__ x, const float* __restrict__ W) {
    int i = blockIdx.x * blockDim.x + threadIdx.x;
    if (i >= NNODES * HID) return;
    int n = i >> 8, c = i & 255;
    g_h[i] = W[x[n] * HID + c];
}

__global__ void k_edge_emb(const float* __restrict__ ea, const float* __restrict__ W,
                           const float* __restrict__ b) {
    int i = blockIdx.x * blockDim.x + threadIdx.x;
    if (i >= NEDGES * HID) return;
    int e = i >> 8, c = i & 255;
    const float* a = ea + e * 4;
    g_e[i] = b[c] + a[0] * W[c] + a[1] * W[HID + c] + a[2] * W[2 * HID + c] + a[3] * W[3 * HID + c];
}

__global__ void k_zinit(const float* __restrict__ eps, int l) {
    int i = blockIdx.x * blockDim.x + threadIdx.x;
    if (i >= NNODES * HID) return;
    g_z[i] = (1.f + eps[l]) * g_h[i];
}

__global__ void k_scatter(const int* __restrict__ src, const int* __restrict__ dst) {
    int i = blockIdx.x * blockDim.x + threadIdx.x;
    if (i >= NEDGES * HID) return;
    int e = i >> 8, c = i & 255;
    float v = g_h[src[e] * HID + c] + g_e[i];
    v = fmaxf(v, 0.f);
    atomicAdd(&g_z[dst[e] * HID + c], v);
}

__global__ void k_zero_cnt() { g_cnt[threadIdx.x] = 0; }

__global__ void k_count(const int* __restrict__ batch) {
    int i = blockIdx.x * blockDim.x + threadIdx.x;
    if (i < NNODES) atomicAdd(&g_cnt[batch[i]], 1);
}

__global__ void k_scan() {
    if (threadIdx.x == 0) {
        int acc = 0;
        for (int g = 0; g < NGRAPHS; g++) { g_start[g] = acc; acc += g_cnt[g]; }
    }
}

__global__ void k_stats(const float* __restrict__ alpha) {
    int g = blockIdx.x, c = threadIdx.x;
    int s = g_start[g], n = g_cnt[g];
    float sum = 0.f, sq = 0.f;
    #pragma unroll 4
    for (int i = 0; i < n; i++) {
        float v = g_h[(size_t)(s + i) * HID + c];
        sum += v; sq += v * v;
    }
    float inv = 1.f / (float)(n > 0 ? n : 1);
    float mu = sum * inv;
    if (alpha) {
        float al = alpha[c];
        float var = sq * inv - (2.f * al - al * al) * mu * mu;
        g_amean[g * HID + c] = al * mu;
        g_rstd[g * HID + c]  = rsqrtf(var + 1e-5f);
    } else {
        g_pool[g * HID + c] = mu;
    }
}

__global__ void k_norm(const int* __restrict__ batch, const float* __restrict__ gamma,
                       const float* __restrict__ beta) {
    int i = blockIdx.x * blockDim.x + threadIdx.x;
    if (i >= NNODES * HID) return;
    int nidx = i >> 8, c = i & 255;
    int g = batch[nidx];
    float v = (g_h[i] - g_amean[g * HID + c]) * g_rstd[g * HID + c];
    g_h[i] = gamma[c] * v + beta[c];
}

// ---------------- head ----------------
__global__ void k_cbio(const float* __restrict__ bio, const float* __restrict__ W1) {
    int j = threadIdx.x;
    float acc = 0.f;
    for (int k = 0; k < BIO; k++) acc += bio[k] * W1[(HID + k) * HID + j];
    g_cbio[j] = acc;
}

__global__ void k_head(const float* __restrict__ W1, const float* __restrict__ b1,
                       const float* __restrict__ W2, const float* __restrict__ b2,
                       float* __restrict__ out) {
    int g = blockIdx.x, j = threadIdx.x;
    __shared__ float sh[HID];
    __shared__ float red[HID];
    sh[j] = g_pool[g * HID + j];
    __syncthreads();
    float acc = b1[j] + g_cbio[j];
    for (int k = 0; k < HID; k++) acc += sh[k] * W1[k * HID + j];
    acc = fmaxf(acc, 0.f);
    red[j] = acc * W2[j];
    __syncthreads();
    for (int st = 128; st > 0; st >>= 1) {
        if (j < st) red[j] += red[j + st];
        __syncthreads();
    }
    if (j == 0) out[g] = red[0] + b2[0];
}

// ---------------- launch ----------------
extern "C" void kernel_launch(void* const* d_in, const int* in_sizes, int n_in,
                              void* d_out, int out_size) {
    const int*   x    = (const int*)d_in[0];
    const int*   ei   = (const int*)d_in[1];
    const float* ea   = (const float*)d_in[2];
    const int*   batch= (const int*)d_in[3];
    const float* nodeW= (const float*)d_in[4];
    const float* eW   = (const float*)d_in[5];
    const float* eb   = (const float*)d_in[6];
    const float* mW1  = (const float*)d_in[7];
    const float* mb1  = (const float*)d_in[8];
    const float* mW2  = (const float*)d_in[9];
    const float* mb2  = (const float*)d_in[10];
    const float* ss   = (const float*)d_in[11];
    const float* cW1  = (const float*)d_in[12];
    const float* cb1  = (const float*)d_in[13];
    const float* cW2  = (const float*)d_in[14];
    const float* cb2  = (const float*)d_in[15];
    const float* ceps = (const float*)d_in[16];
    const float* ng   = (const float*)d_in[17];
    const float* nb   = (const float*)d_in[18];
    const float* na   = (const float*)d_in[19];
    const float* bio  = (const float*)d_in[20];
    const float* hW1  = (const float*)d_in[21];
    const float* hb1  = (const float*)d_in[22];
    const float* hW2  = (const float*)d_in[23];
    const float* hb2  = (const float*)d_in[24];
    float* out = (float*)d_out;

    const int* src = ei;
    const int* dst = ei + NEDGES;

    void *pe, *pt, *ph, *pz, *pwh, *pwl;
    cudaGetSymbolAddress(&pe, g_e);
    cudaGetSymbolAddress(&pt, g_t);
    cudaGetSymbolAddress(&ph, g_h);
    cudaGetSymbolAddress(&pz, g_z);
    cudaGetSymbolAddress(&pwh, g_wt_hi);
    cudaGetSymbolAddress(&pwl, g_wt_lo);
    float* fe = (float*)pe;
    float* ft = (float*)pt;
    float* fh = (float*)ph;
    float* fz = (float*)pz;
    __nv_bfloat16* wh = (__nv_bfloat16*)pwh;
    __nv_bfloat16* wl = (__nv_bfloat16*)pwl;

    const int T = 256;
    int nodeElems = NNODES * HID;
    int edgeElems = NEDGES * HID;

    // pre-split weights (slots: 0=edgeW1, 1=edgeW2, 2+l=convW1[l], 5+l=convW2[l])
    k_wsplit<<<HID, HID>>>(mW1, 0);
    k_wsplit<<<HID, HID>>>(mW2, 1);
    for (int l = 0; l < NLAYERS; l++) {
        k_wsplit<<<HID, HID>>>(cW1 + l * HID * HID, 2 + l);
        k_wsplit<<<HID, HID>>>(cW2 + l * HID * HID, 5 + l);
    }

    // embeddings
    k_node_emb<<<(nodeElems + T - 1) / T, T>>>(x, nodeW);
    k_edge_emb<<<(edgeElems + T - 1) / T, T>>>(ea, eW, eb);

    // edge MLP
    dim3 ge((NEDGES + 127) / 128, 2);
    dim3 gn((NNODES + 127) / 128, 2);
    k_mgemm<1, 0><<<ge, 256>>>(fe, wh + 0 * 65536, wl + 0 * 65536, mb1, ft, NEDGES, nullptr, nullptr);
    k_mgemm<0, 1><<<ge, 256>>>(ft, wh + 1 * 65536, wl + 1 * 65536, mb2, fe, NEDGES, ea, ss);

    // per-graph ranges
    k_zero_cnt<<<1, NGRAPHS>>>();
    k_count<<<(NNODES + T - 1) / T, T>>>(batch);
    k_scan<<<1, 32>>>();

    for (int l = 0; l < NLAYERS; l++) {
        k_zinit<<<(nodeElems + T - 1) / T, T>>>(ceps, l);
        k_scatter<<<(edgeElems + T - 1) / T, T>>>(src, dst);
        k_mgemm<1, 0><<<gn, 256>>>(fz, wh + (size_t)(2 + l) * 65536, wl + (size_t)(2 + l) * 65536,
                                   cb1 + l * HID, ft, NNODES, nullptr, nullptr);
        k_mgemm<0, 0><<<gn, 256>>>(ft, wh + (size_t)(5 + l) * 65536, wl + (size_t)(5 + l) * 65536,
                                   cb2 + l * HID, fh, NNODES, nullptr, nullptr);
        k_stats<<<NGRAPHS, HID>>>(na + l * HID);
        k_norm<<<(nodeElems + T - 1) / T, T>>>(batch, ng + l * HID, nb + l * HID);
    }

    // pool + head
    k_stats<<<NGRAPHS, HID>>>(nullptr);
    k_cbio<<<1, HID>>>(bio, hW1);
    k_head<<<NGRAPHS, HID>>>(hW1, hb1, hW2, hb2, out);
}

// round 4
// speedup vs baseline: 1.8517x; 1.2425x over previous
#include <cuda_runtime.h>
#include <cuda_bf16.h>
#include <cstdint>

#define HID     256
#define NNODES  100000
#define NEDGES  400000
#define NGRAPHS 256
#define NLAYERS 3
#define BIO     512

// ---------------- scratch (device globals; no allocation allowed) ----------------
__device__ float g_e[(size_t)NEDGES * HID];   // edge features (GEMM2 output)
__device__ float g_t[(size_t)NEDGES * HID];   // reused: split bf16 t (hi | lo halves)
__device__ float g_h[(size_t)NNODES * HID];
__device__ float g_z[(size_t)NNODES * HID];
__device__ float g_amean[NGRAPHS * HID];
__device__ float g_rstd[NGRAPHS * HID];
__device__ float g_pool[NGRAPHS * HID];
__device__ float g_cbio[HID];
__device__ int   g_cnt[NGRAPHS];
__device__ int   g_start[NGRAPHS];
// CSR by dst
__device__ int   g_deg[NNODES];
__device__ int   g_fill[NNODES];
__device__ int   g_roff[NNODES + 1];
__device__ int   g_eid[NEDGES];
// pre-transposed + split weights: 8 matrices of [N=256][K=256] bf16
__device__ __nv_bfloat16 g_wt_hi[8 * 65536];
__device__ __nv_bfloat16 g_wt_lo[8 * 65536];

// ---------------- helpers ----------------
__device__ __forceinline__ uint32_t smem_u32(const void* p) {
    uint32_t a;
    asm("{ .reg .u64 t; cvta.to.shared.u64 t, %1; cvt.u32.u64 %0, t; }" : "=r"(a) : "l"(p));
    return a;
}
__device__ __forceinline__ void ldsm4(uint32_t addr, uint32_t* r) {
    asm volatile("ldmatrix.sync.aligned.m8n8.x4.shared.b16 {%0,%1,%2,%3}, [%4];"
                 : "=r"(r[0]), "=r"(r[1]), "=r"(r[2]), "=r"(r[3]) : "r"(addr));
}
__device__ __forceinline__ void mma_bf16(float* d, const uint32_t* a, uint32_t b0, uint32_t b1) {
    asm volatile(
        "mma.sync.aligned.m16n8k16.row.col.f32.bf16.bf16.f32 "
        "{%0,%1,%2,%3}, {%4,%5,%6,%7}, {%8,%9}, {%0,%1,%2,%3};"
        : "+f"(d[0]), "+f"(d[1]), "+f"(d[2]), "+f"(d[3])
        : "r"(a[0]), "r"(a[1]), "r"(a[2]), "r"(a[3]), "r"(b0), "r"(b1));
}

// ---------------- HMMA GEMM: C[M,256] = act(A[M,256] @ W + b) ----------------
// CTA 128(M) x 128(N); 8 warps (4x2), warp tile 32x64. Split precision:
// D += ah*bh + ah*bl + al*bh. A source selected by template:
//   AEMB:   A row r = embB + sum_j eattr[r*4+j] * embW[j*256+:]   (fused edge emb)
//   ASPLIT: A given pre-split as bf16 hi/lo arrays
//   else:   A fp32, split on the fly
// OSPLIT: write C as split bf16 hi/lo instead of fp32.
#define LDB 40  // bf16 per smem row (32 data + 8 pad) = 80 bytes
template <int RELU, int SCALE, int AEMB, int ASPLIT, int OSPLIT>
__global__ __launch_bounds__(256) void k_mgemm(
    const float* __restrict__ A,
    const __nv_bfloat16* __restrict__ Ahi, const __nv_bfloat16* __restrict__ Alo,
    const __nv_bfloat16* __restrict__ Bhi, const __nv_bfloat16* __restrict__ Blo,
    const float* __restrict__ bias, float* __restrict__ C,
    __nv_bfloat16* __restrict__ Chi, __nv_bfloat16* __restrict__ Clo,
    int M, const float* __restrict__ eattr, const float* __restrict__ ss,
    const float* __restrict__ embW, const float* __restrict__ embB) {
    __shared__ __nv_bfloat16 sAhi[128 * LDB];
    __shared__ __nv_bfloat16 sAlo[128 * LDB];
    __shared__ __nv_bfloat16 sBhi[128 * LDB];
    __shared__ __nv_bfloat16 sBlo[128 * LDB];

    const uint32_t AHI = smem_u32(sAhi), ALO = smem_u32(sAlo);
    const uint32_t BHI = smem_u32(sBhi), BLO = smem_u32(sBlo);

    int tid = threadIdx.x, lane = tid & 31, wid = tid >> 5;
    int warpm = wid & 3, warpn = wid >> 2;
    int tile_m = blockIdx.x * 128, bn = blockIdx.y * 128;

    float acc[2][8][4];
    #pragma unroll
    for (int m = 0; m < 2; m++)
        #pragma unroll
        for (int n = 0; n < 8; n++)
            #pragma unroll
            for (int j = 0; j < 4; j++) acc[m][n][j] = 0.f;

    int qgrp = lane >> 2, qidx = lane & 3;

    // ldmatrix per-lane base offsets
    uint32_t aoff = (uint32_t)(warpm * 32 + (lane & 15)) * (LDB * 2) + ((lane >> 4) << 4);
    uint32_t boff = (uint32_t)(warpn * 64 + (lane & 7) + ((lane >> 4) << 3)) * (LDB * 2)
                  + (((lane >> 3) & 1) << 4);

    for (int kc = 0; kc < 8; kc++) {
        int k0 = kc * 32;
        // ---- stage A chunk [128 x 32] into sAhi/sAlo ----
        if (ASPLIT) {
            #pragma unroll
            for (int i = 0; i < 2; i++) {
                int idx = tid + i * 256;             // < 512
                int row = idx >> 2, q = idx & 3;
                int gr = tile_m + row;
                uint4 vh = make_uint4(0, 0, 0, 0), vl = make_uint4(0, 0, 0, 0);
                if (gr < M) {
                    vh = *(const uint4*)(Ahi + (size_t)gr * HID + k0 + q * 8);
                    vl = *(const uint4*)(Alo + (size_t)gr * HID + k0 + q * 8);
                }
                uint32_t off = row * (LDB * 2) + q * 16;
                asm volatile("st.shared.v4.b32 [%0], {%1,%2,%3,%4};"
                             :: "r"(AHI + off), "r"(vh.x), "r"(vh.y), "r"(vh.z), "r"(vh.w));
                asm volatile("st.shared.v4.b32 [%0], {%1,%2,%3,%4};"
                             :: "r"(ALO + off), "r"(vl.x), "r"(vl.y), "r"(vl.z), "r"(vl.w));
            }
        } else {
            #pragma unroll
            for (int i = 0; i < 4; i++) {
                int idx = tid + i * 256;             // < 1024
                int row = idx >> 3, f4 = idx & 7;
                int gr = tile_m + row;
                float4 v = make_float4(0.f, 0.f, 0.f, 0.f);
                if (AEMB) {
                    if (gr < M) {
                        float4 at = *(const float4*)(eattr + (size_t)gr * 4);
                        int kk = k0 + f4 * 4;
                        float4 b4 = *(const float4*)(embB + kk);
                        float4 w0 = *(const float4*)(embW + 0 * HID + kk);
                        float4 w1 = *(const float4*)(embW + 1 * HID + kk);
                        float4 w2 = *(const float4*)(embW + 2 * HID + kk);
                        float4 w3 = *(const float4*)(embW + 3 * HID + kk);
                        v.x = b4.x + at.x * w0.x + at.y * w1.x + at.z * w2.x + at.w * w3.x;
                        v.y = b4.y + at.x * w0.y + at.y * w1.y + at.z * w2.y + at.w * w3.y;
                        v.z = b4.z + at.x * w0.z + at.y * w1.z + at.z * w2.z + at.w * w3.z;
                        v.w = b4.w + at.x * w0.w + at.y * w1.w + at.z * w2.w + at.w * w3.w;
                    }
                } else {
                    if (gr < M) v = *(const float4*)(A + (size_t)gr * HID + k0 + f4 * 4);
                }
                __nv_bfloat162 h01 = __floats2bfloat162_rn(v.x, v.y);
                __nv_bfloat162 h23 = __floats2bfloat162_rn(v.z, v.w);
                __nv_bfloat162 l01 = __floats2bfloat162_rn(v.x - __low2float(h01), v.y - __high2float(h01));
                __nv_bfloat162 l23 = __floats2bfloat162_rn(v.z - __low2float(h23), v.w - __high2float(h23));
                uint32_t off = row * (LDB * 2) + f4 * 8;
                uint32_t u0 = reinterpret_cast<uint32_t&>(h01), u1 = reinterpret_cast<uint32_t&>(h23);
                uint32_t u2 = reinterpret_cast<uint32_t&>(l01), u3 = reinterpret_cast<uint32_t&>(l23);
                asm volatile("st.shared.v2.b32 [%0], {%1,%2};" :: "r"(AHI + off), "r"(u0), "r"(u1));
                asm volatile("st.shared.v2.b32 [%0], {%1,%2};" :: "r"(ALO + off), "r"(u2), "r"(u3));
            }
        }
        // ---- stage B chunk [128(n) x 32(k)] ----
        #pragma unroll
        for (int i = 0; i < 2; i++) {
            int idx = tid + i * 256;
            int row = idx >> 2, q = idx & 3;
            uint4 vh = *(const uint4*)(Bhi + (size_t)(bn + row) * HID + k0 + q * 8);
            uint4 vl = *(const uint4*)(Blo + (size_t)(bn + row) * HID + k0 + q * 8);
            uint32_t off = row * (LDB * 2) + q * 16;
            asm volatile("st.shared.v4.b32 [%0], {%1,%2,%3,%4};"
                         :: "r"(BHI + off), "r"(vh.x), "r"(vh.y), "r"(vh.z), "r"(vh.w));
            asm volatile("st.shared.v4.b32 [%0], {%1,%2,%3,%4};"
                         :: "r"(BLO + off), "r"(vl.x), "r"(vl.y), "r"(vl.z), "r"(vl.w));
        }
        __syncthreads();

        #pragma unroll
        for (int ks = 0; ks < 2; ks++) {
            uint32_t kso = ks * 32;
            uint32_t ah[2][4], al[2][4];
            #pragma unroll
            for (int m = 0; m < 2; m++) {
                uint32_t o = aoff + m * 16 * (LDB * 2) + kso;
                ldsm4(AHI + o, ah[m]);
                ldsm4(ALO + o, al[m]);
            }
            #pragma unroll
            for (int np = 0; np < 4; np++) {
                uint32_t o = boff + np * 16 * (LDB * 2) + kso;
                uint32_t bh[4], bl[4];
                ldsm4(BHI + o, bh);
                ldsm4(BLO + o, bl);
                #pragma unroll
                for (int m = 0; m < 2; m++) {
                    mma_bf16(acc[m][np * 2],     ah[m], bh[0], bh[1]);
                    mma_bf16(acc[m][np * 2],     ah[m], bl[0], bl[1]);
                    mma_bf16(acc[m][np * 2],     al[m], bh[0], bh[1]);
                    mma_bf16(acc[m][np * 2 + 1], ah[m], bh[2], bh[3]);
                    mma_bf16(acc[m][np * 2 + 1], ah[m], bl[2], bl[3]);
                    mma_bf16(acc[m][np * 2 + 1], al[m], bh[2], bh[3]);
                }
            }
        }
        __syncthreads();
    }

    // ---- epilogue ----
    #pragma unroll
    for (int m = 0; m < 2; m++) {
        int r0 = tile_m + warpm * 32 + m * 16 + qgrp;
        int r1 = r0 + 8;
        float rs0 = 1.f, rs1 = 1.f;
        if (SCALE) {
            if (r0 < M) rs0 = (eattr[(size_t)r0 * 4 + 1] > 0.f) ? ss[0] : 1.f;
            if (r1 < M) rs1 = (eattr[(size_t)r1 * 4 + 1] > 0.f) ? ss[0] : 1.f;
        }
        #pragma unroll
        for (int n = 0; n < 8; n++) {
            int col = bn + warpn * 64 + n * 8 + qidx * 2;
            float b0 = __ldg(bias + col), b1 = __ldg(bias + col + 1);
            float v0 = acc[m][n][0] + b0, v1 = acc[m][n][1] + b1;
            float v2 = acc[m][n][2] + b0, v3 = acc[m][n][3] + b1;
            if (RELU) {
                v0 = fmaxf(v0, 0.f); v1 = fmaxf(v1, 0.f);
                v2 = fmaxf(v2, 0.f); v3 = fmaxf(v3, 0.f);
            }
            if (OSPLIT) {
                __nv_bfloat16 h0 = __float2bfloat16(v0), h1 = __float2bfloat16(v1);
                __nv_bfloat16 h2 = __float2bfloat16(v2), h3 = __float2bfloat16(v3);
                __nv_bfloat162 hi0; hi0.x = h0; hi0.y = h1;
                __nv_bfloat162 hi1; hi1.x = h2; hi1.y = h3;
                __nv_bfloat162 lo0 = __floats2bfloat162_rn(v0 - __bfloat162float(h0), v1 - __bfloat162float(h1));
                __nv_bfloat162 lo1 = __floats2bfloat162_rn(v2 - __bfloat162float(h2), v3 - __bfloat162float(h3));
                if (r0 < M) {
                    *(__nv_bfloat162*)(Chi + (size_t)r0 * HID + col) = hi0;
                    *(__nv_bfloat162*)(Clo + (size_t)r0 * HID + col) = lo0;
                }
                if (r1 < M) {
                    *(__nv_bfloat162*)(Chi + (size_t)r1 * HID + col) = hi1;
                    *(__nv_bfloat162*)(Clo + (size_t)r1 * HID + col) = lo1;
                }
            } else {
                if (r0 < M) *(float2*)(C + (size_t)r0 * HID + col) = make_float2(v0 * rs0, v1 * rs0);
                if (r1 < M) *(float2*)(C + (size_t)r1 * HID + col) = make_float2(v2 * rs1, v3 * rs1);
            }
        }
    }
}

// ---------------- weight transpose + split ----------------
__global__ void k_wsplit(const float* __restrict__ W, int slot) {
    int k = blockIdx.x, n = threadIdx.x;
    float v = W[k * HID + n];
    __nv_bfloat16 hi = __float2bfloat16(v);
    __nv_bfloat16 lo = __float2bfloat16(v - __bfloat162float(hi));
    g_wt_hi[(size_t)slot * 65536 + n * HID + k] = hi;
    g_wt_lo[(size_t)slot * 65536 + n * HID + k] = lo;
}

// ---------------- CSR build (by dst) ----------------
__global__ void k_zero_nodes() {
    int i = blockIdx.x * blockDim.x + threadIdx.x;
    if (i < NNODES) { g_deg[i] = 0; g_fill[i] = 0; }
}
__global__ void k_deg(const int* __restrict__ dst) {
    int e = blockIdx.x * blockDim.x + threadIdx.x;
    if (e < NEDGES) atomicAdd(&g_deg[dst[e]], 1);
}
#define SCAN_T 1024
#define SCAN_C ((NNODES + SCAN_T - 1) / SCAN_T)  // 98
__global__ void k_scan_nodes() {
    __shared__ int sm[SCAN_T];
    int t = threadIdx.x;
    int s = t * SCAN_C, e = min(s + SCAN_C, NNODES);
    int local = 0;
    for (int i = s; i < e; i++) local += g_deg[i];
    sm[t] = local;
    __syncthreads();
    // Hillis-Steele inclusive scan
    for (int st = 1; st < SCAN_T; st <<= 1) {
        int v = (t >= st) ? sm[t - st] : 0;
        __syncthreads();
        sm[t] += v;
        __syncthreads();
    }
    int off = (t == 0) ? 0 : sm[t - 1];
    for (int i = s; i < e; i++) { g_roff[i] = off; off += g_deg[i]; }
    if (t == SCAN_T - 1) g_roff[NNODES] = sm[SCAN_T - 1];
}
__global__ void k_fill(const int* __restrict__ dst) {
    int e = blockIdx.x * blockDim.x + threadIdx.x;
    if (e < NEDGES) {
        int d = dst[e];
        int p = g_roff[d] + atomicAdd(&g_fill[d], 1);
        g_eid[p] = e;
    }
}

// ---------------- fused aggregation: z = (1+eps)h + sum_{e->n} relu(h[src]+e) ----------------
__global__ void k_aggregate(const int* __restrict__ src, const float* __restrict__ eps, int l) {
    int node = blockIdx.x * 4 + (threadIdx.x >> 6);
    int c = (threadIdx.x & 63) * 4;
    if (node >= NNODES) return;
    float ep = 1.f + eps[l];
    float4 hv = *(const float4*)(g_h + (size_t)node * HID + c);
    float4 acc = make_float4(ep * hv.x, ep * hv.y, ep * hv.z, ep * hv.w);
    int s0 = g_roff[node], s1 = g_roff[node + 1];
    for (int j = s0; j < s1; j++) {
        int eid = g_eid[j];
        int sn  = src[eid];
        float4 ev = *(const float4*)(g_e + (size_t)eid * HID + c);
        float4 hs = *(const float4*)(g_h + (size_t)sn * HID + c);
        acc.x += fmaxf(ev.x + hs.x, 0.f);
        acc.y += fmaxf(ev.y + hs.y, 0.f);
        acc.z += fmaxf(ev.z + hs.z, 0.f);
        acc.w += fmaxf(ev.w + hs.w, 0.f);
    }
    *(float4*)(g_z + (size_t)node * HID + c) = acc;
}

// ---------------- elementwise / stats ----------------
__global__ void k_node_emb(const int* __restrict__ x, const float* __restrict__ W) {
    int i = blockIdx.x * blockDim.x + threadIdx.x;
    if (i >= NNODES * HID) return;
    int n = i >> 8, c = i & 255;
    g_h[i] = W[x[n] * HID + c];
}

__global__ void k_zero_cnt() { g_cnt[threadIdx.x] = 0; }
__global__ void k_count(const int* __restrict__ batch) {
    int i = blockIdx.x * blockDim.x + threadIdx.x;
    if (i < NNODES) atomicAdd(&g_cnt[batch[i]], 1);
}
__global__ void k_scan() {
    if (threadIdx.x == 0) {
        int acc = 0;
        for (int g = 0; g < NGRAPHS; g++) { g_start[g] = acc; acc += g_cnt[g]; }
    }
}

__global__ void k_stats(const float* __restrict__ alpha) {
    int g = blockIdx.x, c = threadIdx.x;
    int s = g_start[g], n = g_cnt[g];
    float sum = 0.f, sq = 0.f;
    #pragma unroll 4
    for (int i = 0; i < n; i++) {
        float v = g_h[(size_t)(s + i) * HID + c];
        sum += v; sq += v * v;
    }
    float inv = 1.f / (float)(n > 0 ? n : 1);
    float mu = sum * inv;
    if (alpha) {
        float al = alpha[c];
        float var = sq * inv - (2.f * al - al * al) * mu * mu;
        g_amean[g * HID + c] = al * mu;
        g_rstd[g * HID + c]  = rsqrtf(var + 1e-5f);
    } else {
        g_pool[g * HID + c] = mu;
    }
}

__global__ void k_norm(const int* __restrict__ batch, const float* __restrict__ gamma,
                       const float* __restrict__ beta) {
    int i = blockIdx.x * blockDim.x + threadIdx.x;
    if (i >= NNODES * HID) return;
    int nidx = i >> 8, c = i & 255;
    int g = batch[nidx];
    float v = (g_h[i] - g_amean[g * HID + c]) * g_rstd[g * HID + c];
    g_h[i] = gamma[c] * v + beta[c];
}

// ---------------- head ----------------
__global__ void k_cbio(const float* __restrict__ bio, const float* __restrict__ W1) {
    int j = threadIdx.x;
    float acc = 0.f;
    for (int k = 0; k < BIO; k++) acc += bio[k] * W1[(HID + k) * HID + j];
    g_cbio[j] = acc;
}

__global__ void k_head(const float* __restrict__ W1, const float* __restrict__ b1,
                       const float* __restrict__ W2, const float* __restrict__ b2,
                       float* __restrict__ out) {
    int g = blockIdx.x, j = threadIdx.x;
    __shared__ float sh[HID];
    __shared__ float red[HID];
    sh[j] = g_pool[g * HID + j];
    __syncthreads();
    float acc = b1[j] + g_cbio[j];
    for (int k = 0; k < HID; k++) acc += sh[k] * W1[k * HID + j];
    acc = fmaxf(acc, 0.f);
    red[j] = acc * W2[j];
    __syncthreads();
    for (int st = 128; st > 0; st >>= 1) {
        if (j < st) red[j] += red[j + st];
        __syncthreads();
    }
    if (j == 0) out[g] = red[0] + b2[0];
}

// ---------------- launch ----------------
extern "C" void kernel_launch(void* const* d_in, const int* in_sizes, int n_in,
                              void* d_out, int out_size) {
    const int*   x    = (const int*)d_in[0];
    const int*   ei   = (const int*)d_in[1];
    const float* ea   = (const float*)d_in[2];
    const int*   batch= (const int*)d_in[3];
    const float* nodeW= (const float*)d_in[4];
    const float* eW   = (const float*)d_in[5];
    const float* eb   = (const float*)d_in[6];
    const float* mW1  = (const float*)d_in[7];
    const float* mb1  = (const float*)d_in[8];
    const float* mW2  = (const float*)d_in[9];
    const float* mb2  = (const float*)d_in[10];
    const float* ss   = (const float*)d_in[11];
    const float* cW1  = (const float*)d_in[12];
    const float* cb1  = (const float*)d_in[13];
    const float* cW2  = (const float*)d_in[14];
    const float* cb2  = (const float*)d_in[15];
    const float* ceps = (const float*)d_in[16];
    const float* ng   = (const float*)d_in[17];
    const float* nb   = (const float*)d_in[18];
    const float* na   = (const float*)d_in[19];
    const float* bio  = (const float*)d_in[20];
    const float* hW1  = (const float*)d_in[21];
    const float* hb1  = (const float*)d_in[22];
    const float* hW2  = (const float*)d_in[23];
    const float* hb2  = (const float*)d_in[24];
    float* out = (float*)d_out;

    const int* src = ei;
    const int* dst = ei + NEDGES;

    void *pe, *pt, *ph, *pz, *pwh, *pwl;
    cudaGetSymbolAddress(&pe, g_e);
    cudaGetSymbolAddress(&pt, g_t);
    cudaGetSymbolAddress(&ph, g_h);
    cudaGetSymbolAddress(&pz, g_z);
    cudaGetSymbolAddress(&pwh, g_wt_hi);
    cudaGetSymbolAddress(&pwl, g_wt_lo);
    float* fe = (float*)pe;
    float* fh = (float*)ph;
    float* fz = (float*)pz;
    __nv_bfloat16* thi = (__nv_bfloat16*)pt;
    __nv_bfloat16* tlo = thi + (size_t)NEDGES * HID;
    __nv_bfloat16* wh = (__nv_bfloat16*)pwh;
    __nv_bfloat16* wl = (__nv_bfloat16*)pwl;

    const int T = 256;
    int nodeElems = NNODES * HID;

    // pre-split weights (slots: 0=edgeW1, 1=edgeW2, 2+l=convW1[l], 5+l=convW2[l])
    k_wsplit<<<HID, HID>>>(mW1, 0);
    k_wsplit<<<HID, HID>>>(mW2, 1);
    for (int l = 0; l < NLAYERS; l++) {
        k_wsplit<<<HID, HID>>>(cW1 + l * HID * HID, 2 + l);
        k_wsplit<<<HID, HID>>>(cW2 + l * HID * HID, 5 + l);
    }

    // node embedding
    k_node_emb<<<(nodeElems + T - 1) / T, T>>>(x, nodeW);

    // CSR by dst
    k_zero_nodes<<<(NNODES + T - 1) / T, T>>>();
    k_deg<<<(NEDGES + T - 1) / T, T>>>(dst);
    k_scan_nodes<<<1, SCAN_T>>>();
    k_fill<<<(NEDGES + T - 1) / T, T>>>(dst);

    // per-graph ranges (batch sorted)
    k_zero_cnt<<<1, NGRAPHS>>>();
    k_count<<<(NNODES + T - 1) / T, T>>>(batch);
    k_scan<<<1, 32>>>();

    dim3 ge((NEDGES + 127) / 128, 2);
    dim3 gn((NNODES + 127) / 128, 2);

    // edge MLP: GEMM1 fuses edge embedding; t passed split; GEMM2 applies struct scale
    k_mgemm<1, 0, 1, 0, 1><<<ge, 256>>>(nullptr, nullptr, nullptr, wh, wl, mb1,
                                        nullptr, thi, tlo, NEDGES, ea, nullptr, eW, eb);
    k_mgemm<0, 1, 0, 1, 0><<<ge, 256>>>(nullptr, thi, tlo, wh + 65536, wl + 65536, mb2,
                                        fe, nullptr, nullptr, NEDGES, ea, ss, nullptr, nullptr);

    for (int l = 0; l < NLAYERS; l++) {
        k_aggregate<<<(NNODES + 3) / 4, 256>>>(src, ceps, l);
        k_mgemm<1, 0, 0, 0, 1><<<gn, 256>>>(fz, nullptr, nullptr,
                                            wh + (size_t)(2 + l) * 65536, wl + (size_t)(2 + l) * 65536,
                                            cb1 + l * HID, nullptr, thi, tlo, NNODES,
                                            nullptr, nullptr, nullptr, nullptr);
        k_mgemm<0, 0, 0, 1, 0><<<gn, 256>>>(nullptr, thi, tlo,
                                            wh + (size_t)(5 + l) * 65536, wl + (size_t)(5 + l) * 65536,
                                            cb2 + l * HID, fh, nullptr, nullptr, NNODES,
                                            nullptr, nullptr, nullptr, nullptr);
        k_stats<<<NGRAPHS, HID>>>(na + l * HID);
        k_norm<<<(nodeElems + T - 1) / T, T>>>(batch, ng + l * HID, nb + l * HID);
    }

    // pool + head
    k_stats<<<NGRAPHS, HID>>>(nullptr);
    k_cbio<<<1, HID>>>(bio, hW1);
    k_head<<<NGRAPHS, HID>>>(hW1, hb1, hW2, hb2, out);
}

// round 5
// speedup vs baseline: 2.4080x; 1.3004x over previous
#include <cuda_runtime.h>
#include <cuda_bf16.h>
#include <cstdint>

#define HID     256
#define NNODES  100000
#define NEDGES  400000
#define NGRAPHS 256
#define NLAYERS 3
#define BIO     512

// ---------------- scratch (device globals; no allocation allowed) ----------------
__device__ float g_e[(size_t)NEDGES * HID];   // edge features (GEMM2 output)
__device__ float g_t[(size_t)NEDGES * HID];   // reused: split bf16 t (hi | lo halves)
__device__ float g_h[(size_t)NNODES * HID];
__device__ float g_z[(size_t)NNODES * HID];
__device__ float g_amean[NGRAPHS * HID];
__device__ float g_rstd[NGRAPHS * HID];
__device__ float g_mu[NGRAPHS * HID];
__device__ float g_pool[NGRAPHS * HID];
__device__ float g_cbio[HID];
__device__ int   g_cnt[NGRAPHS];
__device__ int   g_start[NGRAPHS];
// CSR by dst
__device__ int   g_deg[NNODES];
__device__ int   g_fill[NNODES];
__device__ int   g_roff[NNODES + 1];
__device__ int   g_eid[NEDGES];
// pre-transposed + split weights: 8 matrices of [N=256][K=256] bf16
__device__ __nv_bfloat16 g_wt_hi[8 * 65536];
__device__ __nv_bfloat16 g_wt_lo[8 * 65536];

// ---------------- helpers ----------------
__device__ __forceinline__ uint32_t smem_u32(const void* p) {
    uint32_t a;
    asm("{ .reg .u64 t; cvta.to.shared.u64 t, %1; cvt.u32.u64 %0, t; }" : "=r"(a) : "l"(p));
    return a;
}
__device__ __forceinline__ void ldsm4(uint32_t addr, uint32_t* r) {
    asm volatile("ldmatrix.sync.aligned.m8n8.x4.shared.b16 {%0,%1,%2,%3}, [%4];"
                 : "=r"(r[0]), "=r"(r[1]), "=r"(r[2]), "=r"(r[3]) : "r"(addr));
}
__device__ __forceinline__ void mma_bf16(float* d, const uint32_t* a, uint32_t b0, uint32_t b1) {
    asm volatile(
        "mma.sync.aligned.m16n8k16.row.col.f32.bf16.bf16.f32 "
        "{%0,%1,%2,%3}, {%4,%5,%6,%7}, {%8,%9}, {%0,%1,%2,%3};"
        : "+f"(d[0]), "+f"(d[1]), "+f"(d[2]), "+f"(d[3])
        : "r"(a[0]), "r"(a[1]), "r"(a[2]), "r"(a[3]), "r"(b0), "r"(b1));
}
__device__ __forceinline__ void cp16(uint32_t d, const void* s) {
    asm volatile("cp.async.cg.shared.global [%0], [%1], 16;" :: "r"(d), "l"(s));
}
__device__ __forceinline__ void cp16z(uint32_t d, const void* s, int sz) {
    asm volatile("cp.async.cg.shared.global [%0], [%1], 16, %2;" :: "r"(d), "l"(s), "r"(sz));
}
#define CP_COMMIT() asm volatile("cp.async.commit_group;" ::: "memory")
#define CP_WAIT0()  asm volatile("cp.async.wait_group 0;" ::: "memory")

// ---------------- HMMA GEMM: C[M,256] = act(A[M,256] @ W + b) ----------------
// CTA 128(M) x 128(N); 8 warps (4x2), warp tile 32x64. Split precision:
// D += ah*bh + ah*bl + al*bh. Double-buffered, cp.async for B (and A if ASPLIT).
#define LDB 40  // bf16 per smem row (32 data + 8 pad) = 80 bytes
#define ABUF 10240u        // bytes per sub-array (128 * 80)
#define BUFSET 40960u      // 4 sub-arrays per buffer set
#define GSMEM (2 * BUFSET) // 81920 bytes dynamic smem
template <int RELU, int SCALE, int AEMB, int ASPLIT, int OSPLIT>
__global__ __launch_bounds__(256) void k_mgemm(
    const float* __restrict__ A,
    const __nv_bfloat16* __restrict__ Ahi, const __nv_bfloat16* __restrict__ Alo,
    const __nv_bfloat16* __restrict__ Bhi, const __nv_bfloat16* __restrict__ Blo,
    const float* __restrict__ bias, float* __restrict__ C,
    __nv_bfloat16* __restrict__ Chi, __nv_bfloat16* __restrict__ Clo,
    int M, const float* __restrict__ eattr, const float* __restrict__ ss,
    const float* __restrict__ embW, const float* __restrict__ embB) {
    extern __shared__ char dyn_smem[];
    const uint32_t base = smem_u32(dyn_smem);

    int tid = threadIdx.x, lane = tid & 31, wid = tid >> 5;
    int warpm = wid & 3, warpn = wid >> 2;
    int tile_m = blockIdx.x * 128, bn = blockIdx.y * 128;

    float acc[2][8][4];
    #pragma unroll
    for (int m = 0; m < 2; m++)
        #pragma unroll
        for (int n = 0; n < 8; n++)
            #pragma unroll
            for (int j = 0; j < 4; j++) acc[m][n][j] = 0.f;

    int qgrp = lane >> 2, qidx = lane & 3;

    // ldmatrix per-lane base offsets (relative to sub-array start)
    uint32_t aoff = (uint32_t)(warpm * 32 + (lane & 15)) * (LDB * 2) + ((lane >> 4) << 4);
    uint32_t boff = (uint32_t)(warpn * 64 + (lane & 7) + ((lane >> 4) << 3)) * (LDB * 2)
                  + (((lane >> 3) & 1) << 4);

    auto stage = [&](int kc, uint32_t sb) {
        int k0 = kc * 32;
        uint32_t sAhi = sb, sAlo = sb + ABUF, sBhi = sb + 2 * ABUF, sBlo = sb + 3 * ABUF;
        // B via cp.async (always pre-split bf16)
        #pragma unroll
        for (int i = 0; i < 2; i++) {
            int idx = tid + i * 256;
            int row = idx >> 2, q = idx & 3;
            uint32_t off = row * (LDB * 2) + q * 16;
            cp16(sBhi + off, Bhi + (size_t)(bn + row) * HID + k0 + q * 8);
            cp16(sBlo + off, Blo + (size_t)(bn + row) * HID + k0 + q * 8);
        }
        if (ASPLIT) {
            #pragma unroll
            for (int i = 0; i < 2; i++) {
                int idx = tid + i * 256;
                int row = idx >> 2, q = idx & 3;
                int gr = tile_m + row;
                int sz = (gr < M) ? 16 : 0;
                uint32_t off = row * (LDB * 2) + q * 16;
                cp16z(sAhi + off, Ahi + (size_t)gr * HID + k0 + q * 8, sz);
                cp16z(sAlo + off, Alo + (size_t)gr * HID + k0 + q * 8, sz);
            }
        } else {
            #pragma unroll
            for (int i = 0; i < 4; i++) {
                int idx = tid + i * 256;
                int row = idx >> 3, f4 = idx & 7;
                int gr = tile_m + row;
                float4 v = make_float4(0.f, 0.f, 0.f, 0.f);
                if (AEMB) {
                    if (gr < M) {
                        float4 at = *(const float4*)(eattr + (size_t)gr * 4);
                        int kk = k0 + f4 * 4;
                        float4 b4 = *(const float4*)(embB + kk);
                        float4 w0 = *(const float4*)(embW + 0 * HID + kk);
                        float4 w1 = *(const float4*)(embW + 1 * HID + kk);
                        float4 w2 = *(const float4*)(embW + 2 * HID + kk);
                        float4 w3 = *(const float4*)(embW + 3 * HID + kk);
                        v.x = b4.x + at.x * w0.x + at.y * w1.x + at.z * w2.x + at.w * w3.x;
                        v.y = b4.y + at.x * w0.y + at.y * w1.y + at.z * w2.y + at.w * w3.y;
                        v.z = b4.z + at.x * w0.z + at.y * w1.z + at.z * w2.z + at.w * w3.z;
                        v.w = b4.w + at.x * w0.w + at.y * w1.w + at.z * w2.w + at.w * w3.w;
                    }
                } else {
                    if (gr < M) v = *(const float4*)(A + (size_t)gr * HID + k0 + f4 * 4);
                }
                __nv_bfloat162 h01 = __floats2bfloat162_rn(v.x, v.y);
                __nv_bfloat162 h23 = __floats2bfloat162_rn(v.z, v.w);
                __nv_bfloat162 l01 = __floats2bfloat162_rn(v.x - __low2float(h01), v.y - __high2float(h01));
                __nv_bfloat162 l23 = __floats2bfloat162_rn(v.z - __low2float(h23), v.w - __high2float(h23));
                uint32_t off = row * (LDB * 2) + f4 * 8;
                uint32_t u0 = reinterpret_cast<uint32_t&>(h01), u1 = reinterpret_cast<uint32_t&>(h23);
                uint32_t u2 = reinterpret_cast<uint32_t&>(l01), u3 = reinterpret_cast<uint32_t&>(l23);
                asm volatile("st.shared.v2.b32 [%0], {%1,%2};" :: "r"(sAhi + off), "r"(u0), "r"(u1));
                asm volatile("st.shared.v2.b32 [%0], {%1,%2};" :: "r"(sAlo + off), "r"(u2), "r"(u3));
            }
        }
    };

    // prologue: stage chunk 0
    stage(0, base);
    CP_COMMIT();
    CP_WAIT0();
    __syncthreads();

    for (int kc = 0; kc < 8; kc++) {
        uint32_t cur = base + (uint32_t)(kc & 1) * BUFSET;
        uint32_t nxt = base + (uint32_t)((kc + 1) & 1) * BUFSET;
        if (kc < 7) { stage(kc + 1, nxt); CP_COMMIT(); }

        uint32_t AHIc = cur, ALOc = cur + ABUF, BHIc = cur + 2 * ABUF, BLOc = cur + 3 * ABUF;
        #pragma unroll
        for (int ks = 0; ks < 2; ks++) {
            uint32_t kso = ks * 32;
            uint32_t ah[2][4], al[2][4];
            #pragma unroll
            for (int m = 0; m < 2; m++) {
                uint32_t o = aoff + m * 16 * (LDB * 2) + kso;
                ldsm4(AHIc + o, ah[m]);
                ldsm4(ALOc + o, al[m]);
            }
            #pragma unroll
            for (int np = 0; np < 4; np++) {
                uint32_t o = boff + np * 16 * (LDB * 2) + kso;
                uint32_t bh[4], bl[4];
                ldsm4(BHIc + o, bh);
                ldsm4(BLOc + o, bl);
                #pragma unroll
                for (int m = 0; m < 2; m++) {
                    mma_bf16(acc[m][np * 2],     ah[m], bh[0], bh[1]);
                    mma_bf16(acc[m][np * 2],     ah[m], bl[0], bl[1]);
                    mma_bf16(acc[m][np * 2],     al[m], bh[0], bh[1]);
                    mma_bf16(acc[m][np * 2 + 1], ah[m], bh[2], bh[3]);
                    mma_bf16(acc[m][np * 2 + 1], ah[m], bl[2], bl[3]);
                    mma_bf16(acc[m][np * 2 + 1], al[m], bh[2], bh[3]);
                }
            }
        }
        if (kc < 7) CP_WAIT0();
        __syncthreads();
    }

    // ---- epilogue ----
    #pragma unroll
    for (int m = 0; m < 2; m++) {
        int r0 = tile_m + warpm * 32 + m * 16 + qgrp;
        int r1 = r0 + 8;
        float rs0 = 1.f, rs1 = 1.f;
        if (SCALE) {
            if (r0 < M) rs0 = (eattr[(size_t)r0 * 4 + 1] > 0.f) ? ss[0] : 1.f;
            if (r1 < M) rs1 = (eattr[(size_t)r1 * 4 + 1] > 0.f) ? ss[0] : 1.f;
        }
        #pragma unroll
        for (int n = 0; n < 8; n++) {
            int col = bn + warpn * 64 + n * 8 + qidx * 2;
            float b0 = __ldg(bias + col), b1 = __ldg(bias + col + 1);
            float v0 = acc[m][n][0] + b0, v1 = acc[m][n][1] + b1;
            float v2 = acc[m][n][2] + b0, v3 = acc[m][n][3] + b1;
            if (RELU) {
                v0 = fmaxf(v0, 0.f); v1 = fmaxf(v1, 0.f);
                v2 = fmaxf(v2, 0.f); v3 = fmaxf(v3, 0.f);
            }
            if (OSPLIT) {
                __nv_bfloat16 h0 = __float2bfloat16(v0), h1 = __float2bfloat16(v1);
                __nv_bfloat16 h2 = __float2bfloat16(v2), h3 = __float2bfloat16(v3);
                __nv_bfloat162 hi0; hi0.x = h0; hi0.y = h1;
                __nv_bfloat162 hi1; hi1.x = h2; hi1.y = h3;
                __nv_bfloat162 lo0 = __floats2bfloat162_rn(v0 - __bfloat162float(h0), v1 - __bfloat162float(h1));
                __nv_bfloat162 lo1 = __floats2bfloat162_rn(v2 - __bfloat162float(h2), v3 - __bfloat162float(h3));
                if (r0 < M) {
                    *(__nv_bfloat162*)(Chi + (size_t)r0 * HID + col) = hi0;
                    *(__nv_bfloat162*)(Clo + (size_t)r0 * HID + col) = lo0;
                }
                if (r1 < M) {
                    *(__nv_bfloat162*)(Chi + (size_t)r1 * HID + col) = hi1;
                    *(__nv_bfloat162*)(Clo + (size_t)r1 * HID + col) = lo1;
                }
            } else {
                if (r0 < M) *(float2*)(C + (size_t)r0 * HID + col) = make_float2(v0 * rs0, v1 * rs0);
                if (r1 < M) *(float2*)(C + (size_t)r1 * HID + col) = make_float2(v2 * rs1, v3 * rs1);
            }
        }
    }
}

// ---------------- weight transpose + split (all 8 in one launch) ----------------
struct WPtrs { const float* p[8]; };
__global__ void k_wsplit_all(WPtrs wp) {
    int slot = blockIdx.y;
    int k = blockIdx.x, n = threadIdx.x;
    float v = wp.p[slot][k * HID + n];
    __nv_bfloat16 hi = __float2bfloat16(v);
    __nv_bfloat16 lo = __float2bfloat16(v - __bfloat162float(hi));
    g_wt_hi[(size_t)slot * 65536 + n * HID + k] = hi;
    g_wt_lo[(size_t)slot * 65536 + n * HID + k] = lo;
}

// ---------------- CSR build (by dst) ----------------
__global__ void k_zero_nodes() {
    int i = blockIdx.x * blockDim.x + threadIdx.x;
    if (i < NNODES) { g_deg[i] = 0; g_fill[i] = 0; }
}
__global__ void k_deg(const int* __restrict__ dst) {
    int e = blockIdx.x * blockDim.x + threadIdx.x;
    if (e < NEDGES) atomicAdd(&g_deg[dst[e]], 1);
}
#define SCAN_T 1024
#define SCAN_C ((NNODES + SCAN_T - 1) / SCAN_T)  // 98
__global__ void k_scan_nodes() {
    __shared__ int sm[SCAN_T];
    int t = threadIdx.x;
    int s = t * SCAN_C, e = min(s + SCAN_C, NNODES);
    int local = 0;
    for (int i = s; i < e; i++) local += g_deg[i];
    sm[t] = local;
    __syncthreads();
    for (int st = 1; st < SCAN_T; st <<= 1) {
        int v = (t >= st) ? sm[t - st] : 0;
        __syncthreads();
        sm[t] += v;
        __syncthreads();
    }
    int off = (t == 0) ? 0 : sm[t - 1];
    for (int i = s; i < e; i++) { g_roff[i] = off; off += g_deg[i]; }
    if (t == SCAN_T - 1) g_roff[NNODES] = sm[SCAN_T - 1];
}
__global__ void k_fill(const int* __restrict__ dst) {
    int e = blockIdx.x * blockDim.x + threadIdx.x;
    if (e < NEDGES) {
        int d = dst[e];
        int p = g_roff[d] + atomicAdd(&g_fill[d], 1);
        g_eid[p] = e;
    }
}

// ---------------- fused aggregation: z = (1+eps)h + sum_{e->n} relu(h[src]+e) ----------------
__global__ void k_aggregate(const int* __restrict__ src, const float* __restrict__ eps, int l) {
    int node = blockIdx.x * 4 + (threadIdx.x >> 6);
    int c = (threadIdx.x & 63) * 4;
    if (node >= NNODES) return;
    float ep = 1.f + eps[l];
    float4 hv = *(const float4*)(g_h + (size_t)node * HID + c);
    float4 acc = make_float4(ep * hv.x, ep * hv.y, ep * hv.z, ep * hv.w);
    int s0 = g_roff[node], s1 = g_roff[node + 1];
    for (int j = s0; j < s1; j++) {
        int eid = g_eid[j];
        int sn  = src[eid];
        float4 ev = *(const float4*)(g_e + (size_t)eid * HID + c);
        float4 hs = *(const float4*)(g_h + (size_t)sn * HID + c);
        acc.x += fmaxf(ev.x + hs.x, 0.f);
        acc.y += fmaxf(ev.y + hs.y, 0.f);
        acc.z += fmaxf(ev.z + hs.z, 0.f);
        acc.w += fmaxf(ev.w + hs.w, 0.f);
    }
    *(float4*)(g_z + (size_t)node * HID + c) = acc;
}

// ---------------- elementwise / stats ----------------
__global__ void k_node_emb(const int* __restrict__ x, const float* __restrict__ W) {
    int i = blockIdx.x * blockDim.x + threadIdx.x;
    if (i >= NNODES * HID) return;
    int n = i >> 8, c = i & 255;
    g_h[i] = W[x[n] * HID + c];
}

__global__ void k_zero_cnt() { g_cnt[threadIdx.x] = 0; }
__global__ void k_count(const int* __restrict__ batch) {
    int i = blockIdx.x * blockDim.x + threadIdx.x;
    if (i < NNODES) atomicAdd(&g_cnt[batch[i]], 1);
}
__global__ void k_scan() {
    if (threadIdx.x == 0) {
        int acc = 0;
        for (int g = 0; g < NGRAPHS; g++) { g_start[g] = acc; acc += g_cnt[g]; }
    }
}

__global__ void k_stats(const float* __restrict__ alpha) {
    int g = blockIdx.x, c = threadIdx.x;
    int s = g_start[g], n = g_cnt[g];
    float sum = 0.f, sq = 0.f;
    #pragma unroll 4
    for (int i = 0; i < n; i++) {
        float v = g_h[(size_t)(s + i) * HID + c];
        sum += v; sq += v * v;
    }
    float inv = 1.f / (float)(n > 0 ? n : 1);
    float mu = sum * inv;
    float al = alpha[c];
    float var = sq * inv - (2.f * al - al * al) * mu * mu;
    g_mu[g * HID + c]    = mu;
    g_amean[g * HID + c] = al * mu;
    g_rstd[g * HID + c]  = rsqrtf(var + 1e-5f);
}

__global__ void k_norm(const int* __restrict__ batch, const float* __restrict__ gamma,
                       const float* __restrict__ beta) {
    int i = blockIdx.x * blockDim.x + threadIdx.x;
    if (i >= NNODES * HID) return;
    int nidx = i >> 8, c = i & 255;
    int g = batch[nidx];
    float v = (g_h[i] - g_amean[g * HID + c]) * g_rstd[g * HID + c];
    g_h[i] = gamma[c] * v + beta[c];
}

// closed-form pool of final GraphNorm: pool = gamma*(mu - amean)*rstd + beta
__global__ void k_poolnorm(const float* __restrict__ gamma, const float* __restrict__ beta) {
    int g = blockIdx.x, c = threadIdx.x;
    float mu = g_mu[g * HID + c];
    g_pool[g * HID + c] = gamma[c] * (mu - g_amean[g * HID + c]) * g_rstd[g * HID + c] + beta[c];
}

// ---------------- head ----------------
__global__ void k_cbio(const float* __restrict__ bio, const float* __restrict__ W1) {
    int j = threadIdx.x;
    float acc = 0.f;
    for (int k = 0; k < BIO; k++) acc += bio[k] * W1[(HID + k) * HID + j];
    g_cbio[j] = acc;
}

__global__ void k_head(const float* __restrict__ W1, const float* __restrict__ b1,
                       const float* __restrict__ W2, const float* __restrict__ b2,
                       float* __restrict__ out) {
    int g = blockIdx.x, j = threadIdx.x;
    __shared__ float sh[HID];
    __shared__ float red[HID];
    sh[j] = g_pool[g * HID + j];
    __syncthreads();
    float acc = b1[j] + g_cbio[j];
    for (int k = 0; k < HID; k++) acc += sh[k] * W1[k * HID + j];
    acc = fmaxf(acc, 0.f);
    red[j] = acc * W2[j];
    __syncthreads();
    for (int st = 128; st > 0; st >>= 1) {
        if (j < st) red[j] += red[j + st];
        __syncthreads();
    }
    if (j == 0) out[g] = red[0] + b2[0];
}

// ---------------- launch ----------------
extern "C" void kernel_launch(void* const* d_in, const int* in_sizes, int n_in,
                              void* d_out, int out_size) {
    const int*   x    = (const int*)d_in[0];
    const int*   ei   = (const int*)d_in[1];
    const float* ea   = (const float*)d_in[2];
    const int*   batch= (const int*)d_in[3];
    const float* nodeW= (const float*)d_in[4];
    const float* eW   = (const float*)d_in[5];
    const float* eb   = (const float*)d_in[6];
    const float* mW1  = (const float*)d_in[7];
    const float* mb1  = (const float*)d_in[8];
    const float* mW2  = (const float*)d_in[9];
    const float* mb2  = (const float*)d_in[10];
    const float* ss   = (const float*)d_in[11];
    const float* cW1  = (const float*)d_in[12];
    const float* cb1  = (const float*)d_in[13];
    const float* cW2  = (const float*)d_in[14];
    const float* cb2  = (const float*)d_in[15];
    const float* ceps = (const float*)d_in[16];
    const float* ng   = (const float*)d_in[17];
    const float* nb   = (const float*)d_in[18];
    const float* na   = (const float*)d_in[19];
    const float* bio  = (const float*)d_in[20];
    const float* hW1  = (const float*)d_in[21];
    const float* hb1  = (const float*)d_in[22];
    const float* hW2  = (const float*)d_in[23];
    const float* hb2  = (const float*)d_in[24];
    float* out = (float*)d_out;

    const int* src = ei;
    const int* dst = ei + NEDGES;

    void *pe, *pt, *ph, *pz, *pwh, *pwl;
    cudaGetSymbolAddress(&pe, g_e);
    cudaGetSymbolAddress(&pt, g_t);
    cudaGetSymbolAddress(&ph, g_h);
    cudaGetSymbolAddress(&pz, g_z);
    cudaGetSymbolAddress(&pwh, g_wt_hi);
    cudaGetSymbolAddress(&pwl, g_wt_lo);
    float* fe = (float*)pe;
    float* fh = (float*)ph;
    float* fz = (float*)pz;
    __nv_bfloat16* thi = (__nv_bfloat16*)pt;
    __nv_bfloat16* tlo = thi + (size_t)NEDGES * HID;
    __nv_bfloat16* wh = (__nv_bfloat16*)pwh;
    __nv_bfloat16* wl = (__nv_bfloat16*)pwl;

    cudaFuncSetAttribute(k_mgemm<1, 0, 1, 0, 1>, cudaFuncAttributeMaxDynamicSharedMemorySize, GSMEM);
    cudaFuncSetAttribute(k_mgemm<0, 1, 0, 1, 0>, cudaFuncAttributeMaxDynamicSharedMemorySize, GSMEM);
    cudaFuncSetAttribute(k_mgemm<1, 0, 0, 0, 1>, cudaFuncAttributeMaxDynamicSharedMemorySize, GSMEM);
    cudaFuncSetAttribute(k_mgemm<0, 0, 0, 1, 0>, cudaFuncAttributeMaxDynamicSharedMemorySize, GSMEM);

    const int T = 256;
    int nodeElems = NNODES * HID;

    // 1: weights (slots: 0=edgeW1, 1=edgeW2, 2+l=convW1[l], 5+l=convW2[l])
    WPtrs wp;
    wp.p[0] = mW1; wp.p[1] = mW2;
    for (int l = 0; l < NLAYERS; l++) { wp.p[2 + l] = cW1 + l * HID * HID; wp.p[5 + l] = cW2 + l * HID * HID; }
    k_wsplit_all<<<dim3(HID, 8), HID>>>(wp);

    // 2-5: CSR by dst
    k_zero_nodes<<<(NNODES + T - 1) / T, T>>>();
    k_deg<<<(NEDGES + T - 1) / T, T>>>(dst);
    k_scan_nodes<<<1, SCAN_T>>>();
    k_fill<<<(NEDGES + T - 1) / T, T>>>(dst);

    dim3 ge((NEDGES + 127) / 128, 2);
    dim3 gn((NNODES + 127) / 128, 2);

    // 6: edge GEMM1 (fused edge embedding) — this is the ncu-profiled launch
    k_mgemm<1, 0, 1, 0, 1><<<ge, 256, GSMEM>>>(nullptr, nullptr, nullptr, wh, wl, mb1,
                                               nullptr, thi, tlo, NEDGES, ea, nullptr, eW, eb);
    // 7: edge GEMM2 (struct scale)
    k_mgemm<0, 1, 0, 1, 0><<<ge, 256, GSMEM>>>(nullptr, thi, tlo, wh + 65536, wl + 65536, mb2,
                                               fe, nullptr, nullptr, NEDGES, ea, ss, nullptr, nullptr);

    // 8: node embedding; 9-11: per-graph ranges
    k_node_emb<<<(nodeElems + T - 1) / T, T>>>(x, nodeW);
    k_zero_cnt<<<1, NGRAPHS>>>();
    k_count<<<(NNODES + T - 1) / T, T>>>(batch);
    k_scan<<<1, 32>>>();

    for (int l = 0; l < NLAYERS; l++) {
        k_aggregate<<<(NNODES + 3) / 4, 256>>>(src, ceps, l);
        k_mgemm<1, 0, 0, 0, 1><<<gn, 256, GSMEM>>>(fz, nullptr, nullptr,
                                                   wh + (size_t)(2 + l) * 65536, wl + (size_t)(2 + l) * 65536,
                                                   cb1 + l * HID, nullptr, thi, tlo, NNODES,
                                                   nullptr, nullptr, nullptr, nullptr);
        k_mgemm<0, 0, 0, 1, 0><<<gn, 256, GSMEM>>>(nullptr, thi, tlo,
                                                   wh + (size_t)(5 + l) * 65536, wl + (size_t)(5 + l) * 65536,
                                                   cb2 + l * HID, fh, nullptr, nullptr, NNODES,
                                                   nullptr, nullptr, nullptr, nullptr);
        k_stats<<<NGRAPHS, HID>>>(na + l * HID);
        if (l < NLAYERS - 1)
            k_norm<<<(nodeElems + T - 1) / T, T>>>(batch, ng + l * HID, nb + l * HID);
    }

    // final pool via closed form + head
    k_poolnorm<<<NGRAPHS, HID>>>(ng + (NLAYERS - 1) * HID, nb + (NLAYERS - 1) * HID);
    k_cbio<<<1, HID>>>(bio, hW1);
    k_head<<<NGRAPHS, HID>>>(hW1, hb1, hW2, hb2, out);
}

// round 9
// speedup vs baseline: 2.4972x; 1.0370x over previous
#include <cuda_runtime.h>
#include <cuda_bf16.h>
#include <cstdint>

#define HID     256
#define NNODES  100000
#define NEDGES  400000
#define NGRAPHS 256
#define NLAYERS 3
#define BIO     512

// ---------------- scratch (device globals; no allocation allowed) ----------------
__device__ float g_e[(size_t)NEDGES * HID];   // edge features (GEMM2 output)
__device__ float g_t[(size_t)NEDGES * HID];   // reused: split bf16 t (hi | lo halves)
__device__ float g_h[(size_t)NNODES * HID];
__device__ float g_z[(size_t)NNODES * HID];   // reused: split bf16 z (hi | lo halves)
__device__ float g_amean[NGRAPHS * HID];
__device__ float g_rstd[NGRAPHS * HID];
__device__ float g_mu[NGRAPHS * HID];
__device__ float g_pool[NGRAPHS * HID];
__device__ float g_cbio[HID];
__device__ int   g_cnt[NGRAPHS];
__device__ int   g_start[NGRAPHS];
// CSR by dst
__device__ int   g_deg[NNODES];
__device__ int   g_fill[NNODES];
__device__ int   g_roff[NNODES + 1];
__device__ int   g_eid[NEDGES];
#define SBLK 256
#define NBLK ((NNODES + SBLK - 1) / SBLK)   // 391
__device__ int   g_bsum[NBLK];
__device__ int   g_boff[NBLK];
// pre-transposed + split weights: 8 matrices of [N=256][K=256] bf16
__device__ __nv_bfloat16 g_wt_hi[8 * 65536];
__device__ __nv_bfloat16 g_wt_lo[8 * 65536];

// ---------------- helpers ----------------
__device__ __forceinline__ uint32_t smem_u32(const void* p) {
    uint32_t a;
    asm("{ .reg .u64 t; cvta.to.shared.u64 t, %1; cvt.u32.u64 %0, t; }" : "=r"(a) : "l"(p));
    return a;
}
__device__ __forceinline__ void ldsm4(uint32_t addr, uint32_t* r) {
    asm volatile("ldmatrix.sync.aligned.m8n8.x4.shared.b16 {%0,%1,%2,%3}, [%4];"
                 : "=r"(r[0]), "=r"(r[1]), "=r"(r[2]), "=r"(r[3]) : "r"(addr));
}
__device__ __forceinline__ void mma_bf16(float* d, const uint32_t* a, uint32_t b0, uint32_t b1) {
    asm volatile(
        "mma.sync.aligned.m16n8k16.row.col.f32.bf16.bf16.f32 "
        "{%0,%1,%2,%3}, {%4,%5,%6,%7}, {%8,%9}, {%0,%1,%2,%3};"
        : "+f"(d[0]), "+f"(d[1]), "+f"(d[2]), "+f"(d[3])
        : "r"(a[0]), "r"(a[1]), "r"(a[2]), "r"(a[3]), "r"(b0), "r"(b1));
}
__device__ __forceinline__ void cp16(uint32_t d, const void* s) {
    asm volatile("cp.async.cg.shared.global [%0], [%1], 16;" :: "r"(d), "l"(s));
}
__device__ __forceinline__ void cp16z(uint32_t d, const void* s, int sz) {
    asm volatile("cp.async.cg.shared.global [%0], [%1], 16, %2;" :: "r"(d), "l"(s), "r"(sz));
}
#define CP_COMMIT() asm volatile("cp.async.commit_group;" ::: "memory")
#define CP_WAIT0()  asm volatile("cp.async.wait_group 0;" ::: "memory")

// ---------------- HMMA GEMM: C[M,256] = act(A[M,256] @ W + b) ----------------
#define LDB 40  // bf16 per smem row (32 data + 8 pad) = 80 bytes
#define ABUF 10240u
#define BUFSET 40960u
#define GSMEM (2 * BUFSET)
template <int RELU, int SCALE, int AEMB, int ASPLIT, int OSPLIT>
__global__ __launch_bounds__(256) void k_mgemm(
    const float* __restrict__ A,
    const __nv_bfloat16* __restrict__ Ahi, const __nv_bfloat16* __restrict__ Alo,
    const __nv_bfloat16* __restrict__ Bhi, const __nv_bfloat16* __restrict__ Blo,
    const float* __restrict__ bias, float* __restrict__ C,
    __nv_bfloat16* __restrict__ Chi, __nv_bfloat16* __restrict__ Clo,
    int M, const float* __restrict__ eattr, const float* __restrict__ ss,
    const float* __restrict__ embW, const float* __restrict__ embB) {
    extern __shared__ char dyn_smem[];
    const uint32_t base = smem_u32(dyn_smem);

    int tid = threadIdx.x, lane = tid & 31, wid = tid >> 5;
    int warpm = wid & 3, warpn = wid >> 2;
    int tile_m = blockIdx.x * 128, bn = blockIdx.y * 128;

    float acc[2][8][4];
    #pragma unroll
    for (int m = 0; m < 2; m++)
        #pragma unroll
        for (int n = 0; n < 8; n++)
            #pragma unroll
            for (int j = 0; j < 4; j++) acc[m][n][j] = 0.f;

    int qgrp = lane >> 2, qidx = lane & 3;
    uint32_t aoff = (uint32_t)(warpm * 32 + (lane & 15)) * (LDB * 2) + ((lane >> 4) << 4);
    uint32_t boff = (uint32_t)(warpn * 64 + (lane & 7) + ((lane >> 4) << 3)) * (LDB * 2)
                  + (((lane >> 3) & 1) << 4);

    auto stage = [&](int kc, uint32_t sb) {
        int k0 = kc * 32;
        uint32_t sAhi = sb, sAlo = sb + ABUF, sBhi = sb + 2 * ABUF, sBlo = sb + 3 * ABUF;
        #pragma unroll
        for (int i = 0; i < 2; i++) {
            int idx = tid + i * 256;
            int row = idx >> 2, q = idx & 3;
            uint32_t off = row * (LDB * 2) + q * 16;
            cp16(sBhi + off, Bhi + (size_t)(bn + row) * HID + k0 + q * 8);
            cp16(sBlo + off, Blo + (size_t)(bn + row) * HID + k0 + q * 8);
        }
        if (ASPLIT) {
            #pragma unroll
            for (int i = 0; i < 2; i++) {
                int idx = tid + i * 256;
                int row = idx >> 2, q = idx & 3;
                int gr = tile_m + row;
                int sz = (gr < M) ? 16 : 0;
                uint32_t off = row * (LDB * 2) + q * 16;
                cp16z(sAhi + off, Ahi + (size_t)gr * HID + k0 + q * 8, sz);
                cp16z(sAlo + off, Alo + (size_t)gr * HID + k0 + q * 8, sz);
            }
        } else {
            #pragma unroll
            for (int i = 0; i < 4; i++) {
                int idx = tid + i * 256;
                int row = idx >> 3, f4 = idx & 7;
                int gr = tile_m + row;
                float4 v = make_float4(0.f, 0.f, 0.f, 0.f);
                if (AEMB) {
                    if (gr < M) {
                        float4 at = *(const float4*)(eattr + (size_t)gr * 4);
                        int kk = k0 + f4 * 4;
                        float4 b4 = *(const float4*)(embB + kk);
                        float4 w0 = *(const float4*)(embW + 0 * HID + kk);
                        float4 w1 = *(const float4*)(embW + 1 * HID + kk);
                        float4 w2 = *(const float4*)(embW + 2 * HID + kk);
                        float4 w3 = *(const float4*)(embW + 3 * HID + kk);
                        v.x = b4.x + at.x * w0.x + at.y * w1.x + at.z * w2.x + at.w * w3.x;
                        v.y = b4.y + at.x * w0.y + at.y * w1.y + at.z * w2.y + at.w * w3.y;
                        v.z = b4.z + at.x * w0.z + at.y * w1.z + at.z * w2.z + at.w * w3.z;
                        v.w = b4.w + at.x * w0.w + at.y * w1.w + at.z * w2.w + at.w * w3.w;
                    }
                } else {
                    if (gr < M) v = *(const float4*)(A + (size_t)gr * HID + k0 + f4 * 4);
                }
                __nv_bfloat162 h01 = __floats2bfloat162_rn(v.x, v.y);
                __nv_bfloat162 h23 = __floats2bfloat162_rn(v.z, v.w);
                __nv_bfloat162 l01 = __floats2bfloat162_rn(v.x - __low2float(h01), v.y - __high2float(h01));
                __nv_bfloat162 l23 = __floats2bfloat162_rn(v.z - __low2float(h23), v.w - __high2float(h23));
                uint32_t off = row * (LDB * 2) + f4 * 8;
                uint32_t u0 = reinterpret_cast<uint32_t&>(h01), u1 = reinterpret_cast<uint32_t&>(h23);
                uint32_t u2 = reinterpret_cast<uint32_t&>(l01), u3 = reinterpret_cast<uint32_t&>(l23);
                asm volatile("st.shared.v2.b32 [%0], {%1,%2};" :: "r"(sAhi + off), "r"(u0), "r"(u1));
                asm volatile("st.shared.v2.b32 [%0], {%1,%2};" :: "r"(sAlo + off), "r"(u2), "r"(u3));
            }
        }
    };

    stage(0, base);
    CP_COMMIT();
    CP_WAIT0();
    __syncthreads();

    for (int kc = 0; kc < 8; kc++) {
        uint32_t cur = base + (uint32_t)(kc & 1) * BUFSET;
        uint32_t nxt = base + (uint32_t)((kc + 1) & 1) * BUFSET;
        if (kc < 7) { stage(kc + 1, nxt); CP_COMMIT(); }

        uint32_t AHIc = cur, ALOc = cur + ABUF, BHIc = cur + 2 * ABUF, BLOc = cur + 3 * ABUF;
        #pragma unroll
        for (int ks = 0; ks < 2; ks++) {
            uint32_t kso = ks * 32;
            uint32_t ah[2][4], al[2][4];
            #pragma unroll
            for (int m = 0; m < 2; m++) {
                uint32_t o = aoff + m * 16 * (LDB * 2) + kso;
                ldsm4(AHIc + o, ah[m]);
                ldsm4(ALOc + o, al[m]);
            }
            #pragma unroll
            for (int np = 0; np < 4; np++) {
                uint32_t o = boff + np * 16 * (LDB * 2) + kso;
                uint32_t bh[4], bl[4];
                ldsm4(BHIc + o, bh);
                ldsm4(BLOc + o, bl);
                #pragma unroll
                for (int m = 0; m < 2; m++) {
                    mma_bf16(acc[m][np * 2],     ah[m], bh[0], bh[1]);
                    mma_bf16(acc[m][np * 2],     ah[m], bl[0], bl[1]);
                    mma_bf16(acc[m][np * 2],     al[m], bh[0], bh[1]);
                    mma_bf16(acc[m][np * 2 + 1], ah[m], bh[2], bh[3]);
                    mma_bf16(acc[m][np * 2 + 1], ah[m], bl[2], bl[3]);
                    mma_bf16(acc[m][np * 2 + 1], al[m], bh[2], bh[3]);
                }
            }
        }
        if (kc < 7) CP_WAIT0();
        __syncthreads();
    }

    // ---- epilogue ----
    #pragma unroll
    for (int m = 0; m < 2; m++) {
        int r0 = tile_m + warpm * 32 + m * 16 + qgrp;
        int r1 = r0 + 8;
        float rs0 = 1.f, rs1 = 1.f;
        if (SCALE) {
            if (r0 < M) rs0 = (eattr[(size_t)r0 * 4 + 1] > 0.f) ? ss[0] : 1.f;
            if (r1 < M) rs1 = (eattr[(size_t)r1 * 4 + 1] > 0.f) ? ss[0] : 1.f;
        }
        #pragma unroll
        for (int n = 0; n < 8; n++) {
            int col = bn + warpn * 64 + n * 8 + qidx * 2;
            float b0 = __ldg(bias + col), b1 = __ldg(bias + col + 1);
            float v0 = acc[m][n][0] + b0, v1 = acc[m][n][1] + b1;
            float v2 = acc[m][n][2] + b0, v3 = acc[m][n][3] + b1;
            if (RELU) {
                v0 = fmaxf(v0, 0.f); v1 = fmaxf(v1, 0.f);
                v2 = fmaxf(v2, 0.f); v3 = fmaxf(v3, 0.f);
            }
            if (OSPLIT) {
                __nv_bfloat16 h0 = __float2bfloat16(v0), h1 = __float2bfloat16(v1);
                __nv_bfloat16 h2 = __float2bfloat16(v2), h3 = __float2bfloat16(v3);
                __nv_bfloat162 hi0; hi0.x = h0; hi0.y = h1;
                __nv_bfloat162 hi1; hi1.x = h2; hi1.y = h3;
                __nv_bfloat162 lo0 = __floats2bfloat162_rn(v0 - __bfloat162float(h0), v1 - __bfloat162float(h1));
                __nv_bfloat162 lo1 = __floats2bfloat162_rn(v2 - __bfloat162float(h2), v3 - __bfloat162float(h3));
                if (r0 < M) {
                    *(__nv_bfloat162*)(Chi + (size_t)r0 * HID + col) = hi0;
                    *(__nv_bfloat162*)(Clo + (size_t)r0 * HID + col) = lo0;
                }
                if (r1 < M) {
                    *(__nv_bfloat162*)(Chi + (size_t)r1 * HID + col) = hi1;
                    *(__nv_bfloat162*)(Clo + (size_t)r1 * HID + col) = lo1;
                }
            } else {
                if (r0 < M) *(float2*)(C + (size_t)r0 * HID + col) = make_float2(v0 * rs0, v1 * rs0);
                if (r1 < M) *(float2*)(C + (size_t)r1 * HID + col) = make_float2(v2 * rs1, v3 * rs1);
            }
        }
    }
}

// ---------------- weight transpose + split ----------------
struct WPtrs { const float* p[8]; };
__global__ void k_wsplit_all(WPtrs wp) {
    int slot = blockIdx.y;
    int k = blockIdx.x, n = threadIdx.x;
    float v = wp.p[slot][k * HID + n];
    __nv_bfloat16 hi = __float2bfloat16(v);
    __nv_bfloat16 lo = __float2bfloat16(v - __bfloat162float(hi));
    g_wt_hi[(size_t)slot * 65536 + n * HID + k] = hi;
    g_wt_lo[(size_t)slot * 65536 + n * HID + k] = lo;
}

// ---------------- CSR build (by dst), hierarchical scan ----------------
__global__ void k_zero_nodes() {
    int i = blockIdx.x * blockDim.x + threadIdx.x;
    if (i < NNODES) { g_deg[i] = 0; g_fill[i] = 0; }
}
__global__ void k_deg(const int* __restrict__ dst) {
    int e = blockIdx.x * blockDim.x + threadIdx.x;
    if (e < NEDGES) atomicAdd(&g_deg[dst[e]], 1);
}
__global__ void k_scan_partial() {
    __shared__ int sm[SBLK];
    int i = blockIdx.x * SBLK + threadIdx.x;
    int v = (i < NNODES) ? g_deg[i] : 0;
    sm[threadIdx.x] = v;
    __syncthreads();
    for (int st = 128; st > 0; st >>= 1) {
        if (threadIdx.x < st) sm[threadIdx.x] += sm[threadIdx.x + st];
        __syncthreads();
    }
    if (threadIdx.x == 0) g_bsum[blockIdx.x] = sm[0];
}
__global__ void k_scan_blocks() {
    __shared__ int sm[512];
    int t = threadIdx.x;
    sm[t] = (t < NBLK) ? g_bsum[t] : 0;
    __syncthreads();
    for (int st = 1; st < 512; st <<= 1) {
        int v = (t >= st) ? sm[t - st] : 0;
        __syncthreads();
        sm[t] += v;
        __syncthreads();
    }
    if (t < NBLK) g_boff[t] = (t == 0) ? 0 : sm[t - 1];
    if (t == 511) g_roff[NNODES] = sm[511];
}
__global__ void k_scan_apply() {
    __shared__ int sm[SBLK];
    int i = blockIdx.x * SBLK + threadIdx.x;
    int v = (i < NNODES) ? g_deg[i] : 0;
    sm[threadIdx.x] = v;
    __syncthreads();
    for (int st = 1; st < SBLK; st <<= 1) {
        int u = (threadIdx.x >= st) ? sm[threadIdx.x - st] : 0;
        __syncthreads();
        sm[threadIdx.x] += u;
        __syncthreads();
    }
    if (i < NNODES) g_roff[i] = g_boff[blockIdx.x] + sm[threadIdx.x] - v;  // exclusive
}
__global__ void k_fill(const int* __restrict__ dst) {
    int e = blockIdx.x * blockDim.x + threadIdx.x;
    if (e < NEDGES) {
        int d = dst[e];
        int p = g_roff[d] + atomicAdd(&g_fill[d], 1);
        g_eid[p] = e;
    }
}

// ---------------- fused aggregation (+ GraphNorm of previous layer when NORM) ----------------
// z = (1+eps) * nh(node) + sum_{e->node} relu(nh(src) + e),  nh = norm(h) or h
// output written pre-split bf16 hi/lo.
template <int NORM>
__global__ void k_aggregate(const int* __restrict__ src, const int* __restrict__ batch,
                            const float* __restrict__ eps, int l,
                            const float* __restrict__ gamma, const float* __restrict__ beta,
                            __nv_bfloat16* __restrict__ zhi, __nv_bfloat16* __restrict__ zlo) {
    int node = blockIdx.x * 4 + (threadIdx.x >> 6);
    int c = (threadIdx.x & 63) * 4;
    if (node >= NNODES) return;
    float ep = 1.f + eps[l];
    float4 ga, be;
    if (NORM) {
        ga = *(const float4*)(gamma + c);
        be = *(const float4*)(beta + c);
    }
    auto loadn = [&](int n) -> float4 {
        float4 hv = *(const float4*)(g_h + (size_t)n * HID + c);
        if (NORM) {
            int g = batch[n];
            float4 am = *(const float4*)(g_amean + g * HID + c);
            float4 rs = *(const float4*)(g_rstd + g * HID + c);
            hv.x = ga.x * (hv.x - am.x) * rs.x + be.x;
            hv.y = ga.y * (hv.y - am.y) * rs.y + be.y;
            hv.z = ga.z * (hv.z - am.z) * rs.z + be.z;
            hv.w = ga.w * (hv.w - am.w) * rs.w + be.w;
        }
        return hv;
    };
    float4 hv = loadn(node);
    float4 acc = make_float4(ep * hv.x, ep * hv.y, ep * hv.z, ep * hv.w);
    int s0 = g_roff[node], s1 = g_roff[node + 1];
    for (int j = s0; j < s1; j++) {
        int eid = g_eid[j];
        float4 ev = *(const float4*)(g_e + (size_t)eid * HID + c);
        float4 hs = loadn(src[eid]);
        acc.x += fmaxf(ev.x + hs.x, 0.f);
        acc.y += fmaxf(ev.y + hs.y, 0.f);
        acc.z += fmaxf(ev.z + hs.z, 0.f);
        acc.w += fmaxf(ev.w + hs.w, 0.f);
    }
    __nv_bfloat16 h0 = __float2bfloat16(acc.x), h1 = __float2bfloat16(acc.y);
    __nv_bfloat16 h2 = __float2bfloat16(acc.z), h3 = __float2bfloat16(acc.w);
    __nv_bfloat162 hiA; hiA.x = h0; hiA.y = h1;
    __nv_bfloat162 hiB; hiB.x = h2; hiB.y = h3;
    __nv_bfloat162 loA = __floats2bfloat162_rn(acc.x - __bfloat162float(h0), acc.y - __bfloat162float(h1));
    __nv_bfloat162 loB = __floats2bfloat162_rn(acc.z - __bfloat162float(h2), acc.w - __bfloat162float(h3));
    *(__nv_bfloat162*)(zhi + (size_t)node * HID + c)     = hiA;
    *(__nv_bfloat162*)(zhi + (size_t)node * HID + c + 2) = hiB;
    *(__nv_bfloat162*)(zlo + (size_t)node * HID + c)     = loA;
    *(__nv_bfloat162*)(zlo + (size_t)node * HID + c + 2) = loB;
}

// ---------------- elementwise / stats ----------------
__global__ void k_node_emb(const int* __restrict__ x, const float* __restrict__ W) {
    int i = blockIdx.x * blockDim.x + threadIdx.x;
    if (i >= NNODES * HID) return;
    int n = i >> 8, c = i & 255;
    g_h[i] = W[x[n] * HID + c];
}

__global__ void k_zero_cnt() { g_cnt[threadIdx.x] = 0; }
__global__ void k_count(const int* __restrict__ batch) {
    int i = blockIdx.x * blockDim.x + threadIdx.x;
    if (i < NNODES) atomicAdd(&g_cnt[batch[i]], 1);
}
__global__ void k_scan() {
    if (threadIdx.x == 0) {
        int acc = 0;
        for (int g = 0; g < NGRAPHS; g++) { g_start[g] = acc; acc += g_cnt[g]; }
    }
}

__global__ void k_stats(const float* __restrict__ alpha) {
    int g = blockIdx.x, c = threadIdx.x;
    int s = g_start[g], n = g_cnt[g];
    float sum = 0.f, sq = 0.f;
    #pragma unroll 4
    for (int i = 0; i < n; i++) {
        float v = g_h[(size_t)(s + i) * HID + c];
        sum += v; sq += v * v;
    }
    float inv = 1.f / (float)(n > 0 ? n : 1);
    float mu = sum * inv;
    float al = alpha[c];
    float var = sq * inv - (2.f * al - al * al) * mu * mu;
    g_mu[g * HID + c]    = mu;
    g_amean[g * HID + c] = al * mu;
    g_rstd[g * HID + c]  = rsqrtf(var + 1e-5f);
}

// closed-form pool of final GraphNorm: pool = gamma*(mu - amean)*rstd + beta
__global__ void k_poolnorm(const float* __restrict__ gamma, const float* __restrict__ beta) {
    int g = blockIdx.x, c = threadIdx.x;
    float mu = g_mu[g * HID + c];
    g_pool[g * HID + c] = gamma[c] * (mu - g_amean[g * HID + c]) * g_rstd[g * HID + c] + beta[c];
}

// ---------------- head ----------------
__global__ void k_cbio(const float* __restrict__ bio, const float* __restrict__ W1) {
    int j = threadIdx.x;
    float acc = 0.f;
    for (int k = 0; k < BIO; k++) acc += bio[k] * W1[(HID + k) * HID + j];
    g_cbio[j] = acc;
}

__global__ void k_head(const float* __restrict__ W1, const float* __restrict__ b1,
                       const float* __restrict__ W2, const float* __restrict__ b2,
                       float* __restrict__ out) {
    int g = blockIdx.x, j = threadIdx.x;
    __shared__ float sh[HID];
    __shared__ float red[HID];
    sh[j] = g_pool[g * HID + j];
    __syncthreads();
    float acc = b1[j] + g_cbio[j];
    for (int k = 0; k < HID; k++) acc += sh[k] * W1[k * HID + j];
    acc = fmaxf(acc, 0.f);
    red[j] = acc * W2[j];
    __syncthreads();
    for (int st = 128; st > 0; st >>= 1) {
        if (j < st) red[j] += red[j + st];
        __syncthreads();
    }
    if (j == 0) out[g] = red[0] + b2[0];
}

// ---------------- launch ----------------
extern "C" void kernel_launch(void* const* d_in, const int* in_sizes, int n_in,
                              void* d_out, int out_size) {
    const int*   x    = (const int*)d_in[0];
    const int*   ei   = (const int*)d_in[1];
    const float* ea   = (const float*)d_in[2];
    const int*   batch= (const int*)d_in[3];
    const float* nodeW= (const float*)d_in[4];
    const float* eW   = (const float*)d_in[5];
    const float* eb   = (const float*)d_in[6];
    const float* mW1  = (const float*)d_in[7];
    const float* mb1  = (const float*)d_in[8];
    const float* mW2  = (const float*)d_in[9];
    const float* mb2  = (const float*)d_in[10];
    const float* ss   = (const float*)d_in[11];
    const float* cW1  = (const float*)d_in[12];
    const float* cb1  = (const float*)d_in[13];
    const float* cW2  = (const float*)d_in[14];
    const float* cb2  = (const float*)d_in[15];
    const float* ceps = (const float*)d_in[16];
    const float* ng   = (const float*)d_in[17];
    const float* nb   = (const float*)d_in[18];
    const float* na   = (const float*)d_in[19];
    const float* bio  = (const float*)d_in[20];
    const float* hW1  = (const float*)d_in[21];
    const float* hb1  = (const float*)d_in[22];
    const float* hW2  = (const float*)d_in[23];
    const float* hb2  = (const float*)d_in[24];
    float* out = (float*)d_out;

    const int* src = ei;
    const int* dst = ei + NEDGES;

    void *pe, *pt, *ph, *pz, *pwh, *pwl;
    cudaGetSymbolAddress(&pe, g_e);
    cudaGetSymbolAddress(&pt, g_t);
    cudaGetSymbolAddress(&ph, g_h);
    cudaGetSymbolAddress(&pz, g_z);
    cudaGetSymbolAddress(&pwh, g_wt_hi);
    cudaGetSymbolAddress(&pwl, g_wt_lo);
    float* fe = (float*)pe;
    float* fh = (float*)ph;
    __nv_bfloat16* thi = (__nv_bfloat16*)pt;
    __nv_bfloat16* tlo = thi + (size_t)NEDGES * HID;
    __nv_bfloat16* zhi = (__nv_bfloat16*)pz;
    __nv_bfloat16* zlo = zhi + (size_t)NNODES * HID;
    __nv_bfloat16* wh = (__nv_bfloat16*)pwh;
    __nv_bfloat16* wl = (__nv_bfloat16*)pwl;

    cudaFuncSetAttribute(k_mgemm<1, 0, 1, 0, 1>, cudaFuncAttributeMaxDynamicSharedMemorySize, GSMEM);
    cudaFuncSetAttribute(k_mgemm<0, 1, 0, 1, 0>, cudaFuncAttributeMaxDynamicSharedMemorySize, GSMEM);
    cudaFuncSetAttribute(k_mgemm<1, 0, 0, 1, 1>, cudaFuncAttributeMaxDynamicSharedMemorySize, GSMEM);
    cudaFuncSetAttribute(k_mgemm<0, 0, 0, 1, 0>, cudaFuncAttributeMaxDynamicSharedMemorySize, GSMEM);

    const int T = 256;
    int nodeElems = NNODES * HID;

    // 1: weights
    WPtrs wp;
    wp.p[0] = mW1; wp.p[1] = mW2;
    for (int l = 0; l < NLAYERS; l++) { wp.p[2 + l] = cW1 + l * HID * HID; wp.p[5 + l] = cW2 + l * HID * HID; }
    k_wsplit_all<<<dim3(HID, 8), HID>>>(wp);

    // 2-5
    k_zero_nodes<<<(NNODES + T - 1) / T, T>>>();
    k_deg<<<(NEDGES + T - 1) / T, T>>>(dst);
    k_scan_partial<<<NBLK, SBLK>>>();
    k_scan_blocks<<<1, 512>>>();

    dim3 ge((NEDGES + 127) / 128, 2);
    dim3 gn((NNODES + 127) / 128, 2);

    // 6: edge GEMM1 (profiled by ncu -s 5 -c 1)
    k_mgemm<1, 0, 1, 0, 1><<<ge, 256, GSMEM>>>(nullptr, nullptr, nullptr, wh, wl, mb1,
                                               nullptr, thi, tlo, NEDGES, ea, nullptr, eW, eb);
    // 7-8: finish CSR
    k_scan_apply<<<NBLK, SBLK>>>();
    k_fill<<<(NEDGES + T - 1) / T, T>>>(dst);
    // 9: edge GEMM2
    k_mgemm<0, 1, 0, 1, 0><<<ge, 256, GSMEM>>>(nullptr, thi, tlo, wh + 65536, wl + 65536, mb2,
                                               fe, nullptr, nullptr, NEDGES, ea, ss, nullptr, nullptr);

    // node embedding; per-graph ranges
    k_node_emb<<<(nodeElems + T - 1) / T, T>>>(x, nodeW);
    k_zero_cnt<<<1, NGRAPHS>>>();
    k_count<<<(NNODES + T - 1) / T, T>>>(batch);
    k_scan<<<1, 32>>>();

    for (int l = 0; l < NLAYERS; l++) {
        if (l == 0)
            k_aggregate<0><<<(NNODES + 3) / 4, 256>>>(src, batch, ceps, l, nullptr, nullptr, zhi, zlo);
        else
            k_aggregate<1><<<(NNODES + 3) / 4, 256>>>(src, batch, ceps, l,
                                                      ng + (l - 1) * HID, nb + (l - 1) * HID, zhi, zlo);
        k_mgemm<1, 0, 0, 1, 1><<<gn, 256, GSMEM>>>(nullptr, zhi, zlo,
                                                   wh + (size_t)(2 + l) * 65536, wl + (size_t)(2 + l) * 65536,
                                                   cb1 + l * HID, nullptr, thi, tlo, NNODES,
                                                   nullptr, nullptr, nullptr, nullptr);
        k_mgemm<0, 0, 0, 1, 0><<<gn, 256, GSMEM>>>(nullptr, thi, tlo,
                                                   wh + (size_t)(5 + l) * 65536, wl + (size_t)(5 + l) * 65536,
                                                   cb2 + l * HID, fh, nullptr, nullptr, NNODES,
                                                   nullptr, nullptr, nullptr, nullptr);
        k_stats<<<NGRAPHS, HID>>>(na + l * HID);
    }

    // final pool via closed form + head
    k_poolnorm<<<NGRAPHS, HID>>>(ng + (NLAYERS - 1) * HID, nb + (NLAYERS - 1) * HID);
    k_cbio<<<1, HID>>>(bio, hW1);
    k_head<<<NGRAPHS, HID>>>(hW1, hb1, hW2, hb2, out);
}

// round 14
// speedup vs baseline: 2.9708x; 1.1897x over previous
#include <cuda_runtime.h>
#include <cuda_bf16.h>
#include <cstdint>

#define HID     256
#define NNODES  100000
#define NEDGES  400000
#define NGRAPHS 256
#define NLAYERS 3
#define BIO     512

// ---------------- scratch (device globals; no allocation allowed) ----------------
__device__ float g_e[(size_t)NEDGES * HID];   // edge features (GEMM2 output)
__device__ float g_t[(size_t)NEDGES * HID];   // reused: split bf16 t (hi | lo halves) for node MLP
__device__ float g_h[(size_t)NNODES * HID];
__device__ float g_z[(size_t)NNODES * HID];   // reused: split bf16 z (hi | lo halves)
__device__ float g_amean[NGRAPHS * HID];
__device__ float g_rstd[NGRAPHS * HID];
__device__ float g_mu[NGRAPHS * HID];
__device__ float g_pool[NGRAPHS * HID];
__device__ float g_cbio[HID];
__device__ float g_w1eff[4 * HID];            // EW @ W1  (folded edge GEMM1)
__device__ float g_b1eff[HID];                // eb @ W1 + b1
__device__ int   g_cnt[NGRAPHS];
__device__ int   g_start[NGRAPHS];
// CSR by dst
__device__ int   g_deg[NNODES];
__device__ int   g_fill[NNODES];
__device__ int   g_roff[NNODES + 1];
__device__ int   g_eid[NEDGES];
#define SBLK 256
#define NBLK ((NNODES + SBLK - 1) / SBLK)   // 391
__device__ int   g_bsum[NBLK];
__device__ int   g_boff[NBLK];
// pre-transposed + split weights: 8 matrices of [N=256][K=256] bf16
__device__ __nv_bfloat16 g_wt_hi[8 * 65536];
__device__ __nv_bfloat16 g_wt_lo[8 * 65536];

// ---------------- helpers ----------------
__device__ __forceinline__ uint32_t smem_u32(const void* p) {
    uint32_t a;
    asm("{ .reg .u64 t; cvta.to.shared.u64 t, %1; cvt.u32.u64 %0, t; }" : "=r"(a) : "l"(p));
    return a;
}
__device__ __forceinline__ void ldsm4(uint32_t addr, uint32_t* r) {
    asm volatile("ldmatrix.sync.aligned.m8n8.x4.shared.b16 {%0,%1,%2,%3}, [%4];"
                 : "=r"(r[0]), "=r"(r[1]), "=r"(r[2]), "=r"(r[3]) : "r"(addr));
}
__device__ __forceinline__ void mma_bf16(float* d, const uint32_t* a, uint32_t b0, uint32_t b1) {
    asm volatile(
        "mma.sync.aligned.m16n8k16.row.col.f32.bf16.bf16.f32 "
        "{%0,%1,%2,%3}, {%4,%5,%6,%7}, {%8,%9}, {%0,%1,%2,%3};"
        : "+f"(d[0]), "+f"(d[1]), "+f"(d[2]), "+f"(d[3])
        : "r"(a[0]), "r"(a[1]), "r"(a[2]), "r"(a[3]), "r"(b0), "r"(b1));
}
__device__ __forceinline__ void cp16(uint32_t d, const void* s) {
    asm volatile("cp.async.cg.shared.global [%0], [%1], 16;" :: "r"(d), "l"(s));
}
__device__ __forceinline__ void cp16z(uint32_t d, const void* s, int sz) {
    asm volatile("cp.async.cg.shared.global [%0], [%1], 16, %2;" :: "r"(d), "l"(s), "r"(sz));
}
#define CP_COMMIT() asm volatile("cp.async.commit_group;" ::: "memory")
#define CP_WAIT0()  asm volatile("cp.async.wait_group 0;" ::: "memory")

// ---------------- HMMA GEMM: C[M,256] = act(A[M,256] @ W + b) ----------------
// AEMB=1: A row r computed on the fly as relu(b1eff + sum_i ea[r,i]*W1eff[i,:])
//         (the folded edge-MLP first layer).
// ASPLIT=1: A given pre-split bf16 hi/lo (cp.async path).
// OSPLIT=1: write C split bf16 hi/lo.
#define LDB 40  // bf16 per smem row (32 data + 8 pad) = 80 bytes
#define ABUF 10240u
#define BUFSET 40960u
#define GSMEM (2 * BUFSET)
template <int RELU, int SCALE, int AEMB, int ASPLIT, int OSPLIT>
__global__ __launch_bounds__(256) void k_mgemm(
    const float* __restrict__ A,
    const __nv_bfloat16* __restrict__ Ahi, const __nv_bfloat16* __restrict__ Alo,
    const __nv_bfloat16* __restrict__ Bhi, const __nv_bfloat16* __restrict__ Blo,
    const float* __restrict__ bias, float* __restrict__ C,
    __nv_bfloat16* __restrict__ Chi, __nv_bfloat16* __restrict__ Clo,
    int M, const float* __restrict__ eattr, const float* __restrict__ ss) {
    extern __shared__ char dyn_smem[];
    const uint32_t base = smem_u32(dyn_smem);

    int tid = threadIdx.x, lane = tid & 31, wid = tid >> 5;
    int warpm = wid & 3, warpn = wid >> 2;
    int tile_m = blockIdx.x * 128, bn = blockIdx.y * 128;

    float acc[2][8][4];
    #pragma unroll
    for (int m = 0; m < 2; m++)
        #pragma unroll
        for (int n = 0; n < 8; n++)
            #pragma unroll
            for (int j = 0; j < 4; j++) acc[m][n][j] = 0.f;

    int qgrp = lane >> 2, qidx = lane & 3;
    uint32_t aoff = (uint32_t)(warpm * 32 + (lane & 15)) * (LDB * 2) + ((lane >> 4) << 4);
    uint32_t boff = (uint32_t)(warpn * 64 + (lane & 7) + ((lane >> 4) << 3)) * (LDB * 2)
                  + (((lane >> 3) & 1) << 4);

    auto stage = [&](int kc, uint32_t sb) {
        int k0 = kc * 32;
        uint32_t sAhi = sb, sAlo = sb + ABUF, sBhi = sb + 2 * ABUF, sBlo = sb + 3 * ABUF;
        #pragma unroll
        for (int i = 0; i < 2; i++) {
            int idx = tid + i * 256;
            int row = idx >> 2, q = idx & 3;
            uint32_t off = row * (LDB * 2) + q * 16;
            cp16(sBhi + off, Bhi + (size_t)(bn + row) * HID + k0 + q * 8);
            cp16(sBlo + off, Blo + (size_t)(bn + row) * HID + k0 + q * 8);
        }
        if (ASPLIT) {
            #pragma unroll
            for (int i = 0; i < 2; i++) {
                int idx = tid + i * 256;
                int row = idx >> 2, q = idx & 3;
                int gr = tile_m + row;
                int sz = (gr < M) ? 16 : 0;
                uint32_t off = row * (LDB * 2) + q * 16;
                cp16z(sAhi + off, Ahi + (size_t)gr * HID + k0 + q * 8, sz);
                cp16z(sAlo + off, Alo + (size_t)gr * HID + k0 + q * 8, sz);
            }
        } else {
            #pragma unroll
            for (int i = 0; i < 4; i++) {
                int idx = tid + i * 256;
                int row = idx >> 3, f4 = idx & 7;
                int gr = tile_m + row;
                float4 v = make_float4(0.f, 0.f, 0.f, 0.f);
                if (AEMB) {
                    if (gr < M) {
                        float4 at = *(const float4*)(eattr + (size_t)gr * 4);
                        int kk = k0 + f4 * 4;
                        float4 b4 = *(const float4*)(g_b1eff + kk);
                        float4 w0 = *(const float4*)(g_w1eff + 0 * HID + kk);
                        float4 w1 = *(const float4*)(g_w1eff + 1 * HID + kk);
                        float4 w2 = *(const float4*)(g_w1eff + 2 * HID + kk);
                        float4 w3 = *(const float4*)(g_w1eff + 3 * HID + kk);
                        v.x = fmaxf(b4.x + at.x * w0.x + at.y * w1.x + at.z * w2.x + at.w * w3.x, 0.f);
                        v.y = fmaxf(b4.y + at.x * w0.y + at.y * w1.y + at.z * w2.y + at.w * w3.y, 0.f);
                        v.z = fmaxf(b4.z + at.x * w0.z + at.y * w1.z + at.z * w2.z + at.w * w3.z, 0.f);
                        v.w = fmaxf(b4.w + at.x * w0.w + at.y * w1.w + at.z * w2.w + at.w * w3.w, 0.f);
                    }
                } else {
                    if (gr < M) v = *(const float4*)(A + (size_t)gr * HID + k0 + f4 * 4);
                }
                __nv_bfloat162 h01 = __floats2bfloat162_rn(v.x, v.y);
                __nv_bfloat162 h23 = __floats2bfloat162_rn(v.z, v.w);
                __nv_bfloat162 l01 = __floats2bfloat162_rn(v.x - __low2float(h01), v.y - __high2float(h01));
                __nv_bfloat162 l23 = __floats2bfloat162_rn(v.z - __low2float(h23), v.w - __high2float(h23));
                uint32_t off = row * (LDB * 2) + f4 * 8;
                uint32_t u0 = reinterpret_cast<uint32_t&>(h01), u1 = reinterpret_cast<uint32_t&>(h23);
                uint32_t u2 = reinterpret_cast<uint32_t&>(l01), u3 = reinterpret_cast<uint32_t&>(l23);
                asm volatile("st.shared.v2.b32 [%0], {%1,%2};" :: "r"(sAhi + off), "r"(u0), "r"(u1));
                asm volatile("st.shared.v2.b32 [%0], {%1,%2};" :: "r"(sAlo + off), "r"(u2), "r"(u3));
            }
        }
    };

    stage(0, base);
    CP_COMMIT();
    CP_WAIT0();
    __syncthreads();

    for (int kc = 0; kc < 8; kc++) {
        uint32_t cur = base + (uint32_t)(kc & 1) * BUFSET;
        uint32_t nxt = base + (uint32_t)((kc + 1) & 1) * BUFSET;
        if (kc < 7) { stage(kc + 1, nxt); CP_COMMIT(); }

        uint32_t AHIc = cur, ALOc = cur + ABUF, BHIc = cur + 2 * ABUF, BLOc = cur + 3 * ABUF;
        #pragma unroll
        for (int ks = 0; ks < 2; ks++) {
            uint32_t kso = ks * 32;
            uint32_t ah[2][4], al[2][4];
            #pragma unroll
            for (int m = 0; m < 2; m++) {
                uint32_t o = aoff + m * 16 * (LDB * 2) + kso;
                ldsm4(AHIc + o, ah[m]);
                ldsm4(ALOc + o, al[m]);
            }
            #pragma unroll
            for (int np = 0; np < 4; np++) {
                uint32_t o = boff + np * 16 * (LDB * 2) + kso;
                uint32_t bh[4], bl[4];
                ldsm4(BHIc + o, bh);
                ldsm4(BLOc + o, bl);
                #pragma unroll
                for (int m = 0; m < 2; m++) {
                    mma_bf16(acc[m][np * 2],     ah[m], bh[0], bh[1]);
                    mma_bf16(acc[m][np * 2],     ah[m], bl[0], bl[1]);
                    mma_bf16(acc[m][np * 2],     al[m], bh[0], bh[1]);
                    mma_bf16(acc[m][np * 2 + 1], ah[m], bh[2], bh[3]);
                    mma_bf16(acc[m][np * 2 + 1], ah[m], bl[2], bl[3]);
                    mma_bf16(acc[m][np * 2 + 1], al[m], bh[2], bh[3]);
                }
            }
        }
        if (kc < 7) CP_WAIT0();
        __syncthreads();
    }

    // ---- epilogue ----
    #pragma unroll
    for (int m = 0; m < 2; m++) {
        int r0 = tile_m + warpm * 32 + m * 16 + qgrp;
        int r1 = r0 + 8;
        float rs0 = 1.f, rs1 = 1.f;
        if (SCALE) {
            if (r0 < M) rs0 = (eattr[(size_t)r0 * 4 + 1] > 0.f) ? ss[0] : 1.f;
            if (r1 < M) rs1 = (eattr[(size_t)r1 * 4 + 1] > 0.f) ? ss[0] : 1.f;
        }
        #pragma unroll
        for (int n = 0; n < 8; n++) {
            int col = bn + warpn * 64 + n * 8 + qidx * 2;
            float b0 = __ldg(bias + col), b1 = __ldg(bias + col + 1);
            float v0 = acc[m][n][0] + b0, v1 = acc[m][n][1] + b1;
            float v2 = acc[m][n][2] + b0, v3 = acc[m][n][3] + b1;
            if (RELU) {
                v0 = fmaxf(v0, 0.f); v1 = fmaxf(v1, 0.f);
                v2 = fmaxf(v2, 0.f); v3 = fmaxf(v3, 0.f);
            }
            if (OSPLIT) {
                __nv_bfloat16 h0 = __float2bfloat16(v0), h1 = __float2bfloat16(v1);
                __nv_bfloat16 h2 = __float2bfloat16(v2), h3 = __float2bfloat16(v3);
                __nv_bfloat162 hi0; hi0.x = h0; hi0.y = h1;
                __nv_bfloat162 hi1; hi1.x = h2; hi1.y = h3;
                __nv_bfloat162 lo0 = __floats2bfloat162_rn(v0 - __bfloat162float(h0), v1 - __bfloat162float(h1));
                __nv_bfloat162 lo1 = __floats2bfloat162_rn(v2 - __bfloat162float(h2), v3 - __bfloat162float(h3));
                if (r0 < M) {
                    *(__nv_bfloat162*)(Chi + (size_t)r0 * HID + col) = hi0;
                    *(__nv_bfloat162*)(Clo + (size_t)r0 * HID + col) = lo0;
                }
                if (r1 < M) {
                    *(__nv_bfloat162*)(Chi + (size_t)r1 * HID + col) = hi1;
                    *(__nv_bfloat162*)(Clo + (size_t)r1 * HID + col) = lo1;
                }
            } else {
                if (r0 < M) *(float2*)(C + (size_t)r0 * HID + col) = make_float2(v0 * rs0, v1 * rs0);
                if (r1 < M) *(float2*)(C + (size_t)r1 * HID + col) = make_float2(v2 * rs1, v3 * rs1);
            }
        }
    }
}

// ---------------- weight transpose + split ----------------
struct WPtrs { const float* p[8]; };
__global__ void k_wsplit_all(WPtrs wp) {
    int slot = blockIdx.y;
    int k = blockIdx.x, n = threadIdx.x;
    float v = wp.p[slot][k * HID + n];
    __nv_bfloat16 hi = __float2bfloat16(v);
    __nv_bfloat16 lo = __float2bfloat16(v - __bfloat162float(hi));
    g_wt_hi[(size_t)slot * 65536 + n * HID + k] = hi;
    g_wt_lo[(size_t)slot * 65536 + n * HID + k] = lo;
}

// ---------------- fold edge embedding into edge-MLP layer 1 ----------------
// W1eff[i][j] = sum_k EW[i][k] * W1[k][j];  b1eff[j] = sum_k eb[k] * W1[k][j] + b1[j]
__global__ void k_wfold(const float* __restrict__ EW, const float* __restrict__ ebias,
                        const float* __restrict__ W1, const float* __restrict__ b1) {
    int j = threadIdx.x;  // 1 block x 256 threads
    float a0 = 0.f, a1 = 0.f, a2 = 0.f, a3 = 0.f, ab = 0.f;
    for (int k = 0; k < HID; k++) {
        float w = W1[k * HID + j];
        a0 += EW[0 * HID + k] * w;
        a1 += EW[1 * HID + k] * w;
        a2 += EW[2 * HID + k] * w;
        a3 += EW[3 * HID + k] * w;
        ab += ebias[k] * w;
    }
    g_w1eff[0 * HID + j] = a0;
    g_w1eff[1 * HID + j] = a1;
    g_w1eff[2 * HID + j] = a2;
    g_w1eff[3 * HID + j] = a3;
    g_b1eff[j] = ab + b1[j];
}

// ---------------- CSR build (by dst), hierarchical scan ----------------
__global__ void k_zero_nodes() {
    int i = blockIdx.x * blockDim.x + threadIdx.x;
    if (i < NNODES) { g_deg[i] = 0; g_fill[i] = 0; }
}
__global__ void k_deg(const int* __restrict__ dst) {
    int e = blockIdx.x * blockDim.x + threadIdx.x;
    if (e < NEDGES) atomicAdd(&g_deg[dst[e]], 1);
}
__global__ void k_scan_partial() {
    __shared__ int sm[SBLK];
    int i = blockIdx.x * SBLK + threadIdx.x;
    int v = (i < NNODES) ? g_deg[i] : 0;
    sm[threadIdx.x] = v;
    __syncthreads();
    for (int st = 128; st > 0; st >>= 1) {
        if (threadIdx.x < st) sm[threadIdx.x] += sm[threadIdx.x + st];
        __syncthreads();
    }
    if (threadIdx.x == 0) g_bsum[blockIdx.x] = sm[0];
}
__global__ void k_scan_blocks() {
    __shared__ int sm[512];
    int t = threadIdx.x;
    sm[t] = (t < NBLK) ? g_bsum[t] : 0;
    __syncthreads();
    for (int st = 1; st < 512; st <<= 1) {
        int v = (t >= st) ? sm[t - st] : 0;
        __syncthreads();
        sm[t] += v;
        __syncthreads();
    }
    if (t < NBLK) g_boff[t] = (t == 0) ? 0 : sm[t - 1];
    if (t == 511) g_roff[NNODES] = sm[511];
}
__global__ void k_scan_apply() {
    __shared__ int sm[SBLK];
    int i = blockIdx.x * SBLK + threadIdx.x;
    int v = (i < NNODES) ? g_deg[i] : 0;
    sm[threadIdx.x] = v;
    __syncthreads();
    for (int st = 1; st < SBLK; st <<= 1) {
        int u = (threadIdx.x >= st) ? sm[threadIdx.x - st] : 0;
        __syncthreads();
        sm[threadIdx.x] += u;
        __syncthreads();
    }
    if (i < NNODES) g_roff[i] = g_boff[blockIdx.x] + sm[threadIdx.x] - v;  // exclusive
}
__global__ void k_fill(const int* __restrict__ dst) {
    int e = blockIdx.x * blockDim.x + threadIdx.x;
    if (e < NEDGES) {
        int d = dst[e];
        int p = g_roff[d] + atomicAdd(&g_fill[d], 1);
        g_eid[p] = e;
    }
}

// ---------------- fused aggregation (+ GraphNorm of previous layer when NORM) ----------------
template <int NORM>
__global__ void k_aggregate(const int* __restrict__ src, const int* __restrict__ batch,
                            const float* __restrict__ eps, int l,
                            const float* __restrict__ gamma, const float* __restrict__ beta,
                            __nv_bfloat16* __restrict__ zhi, __nv_bfloat16* __restrict__ zlo) {
    int node = blockIdx.x * 4 + (threadIdx.x >> 6);
    int c = (threadIdx.x & 63) * 4;
    if (node >= NNODES) return;
    float ep = 1.f + eps[l];
    float4 ga, be;
    if (NORM) {
        ga = *(const float4*)(gamma + c);
        be = *(const float4*)(beta + c);
    }
    auto loadn = [&](int n) -> float4 {
        float4 hv = *(const float4*)(g_h + (size_t)n * HID + c);
        if (NORM) {
            int g = batch[n];
            float4 am = *(const float4*)(g_amean + g * HID + c);
            float4 rs = *(const float4*)(g_rstd + g * HID + c);
            hv.x = ga.x * (hv.x - am.x) * rs.x + be.x;
            hv.y = ga.y * (hv.y - am.y) * rs.y + be.y;
            hv.z = ga.z * (hv.z - am.z) * rs.z + be.z;
            hv.w = ga.w * (hv.w - am.w) * rs.w + be.w;
        }
        return hv;
    };
    float4 hv = loadn(node);
    float4 acc = make_float4(ep * hv.x, ep * hv.y, ep * hv.z, ep * hv.w);
    int s0 = g_roff[node], s1 = g_roff[node + 1];
    for (int j = s0; j < s1; j++) {
        int eid = g_eid[j];
        float4 ev = *(const float4*)(g_e + (size_t)eid * HID + c);
        float4 hs = loadn(src[eid]);
        acc.x += fmaxf(ev.x + hs.x, 0.f);
        acc.y += fmaxf(ev.y + hs.y, 0.f);
        acc.z += fmaxf(ev.z + hs.z, 0.f);
        acc.w += fmaxf(ev.w + hs.w, 0.f);
    }
    __nv_bfloat16 h0 = __float2bfloat16(acc.x), h1 = __float2bfloat16(acc.y);
    __nv_bfloat16 h2 = __float2bfloat16(acc.z), h3 = __float2bfloat16(acc.w);
    __nv_bfloat162 hiA; hiA.x = h0; hiA.y = h1;
    __nv_bfloat162 hiB; hiB.x = h2; hiB.y = h3;
    __nv_bfloat162 loA = __floats2bfloat162_rn(acc.x - __bfloat162float(h0), acc.y - __bfloat162float(h1));
    __nv_bfloat162 loB = __floats2bfloat162_rn(acc.z - __bfloat162float(h2), acc.w - __bfloat162float(h3));
    *(__nv_bfloat162*)(zhi + (size_t)node * HID + c)     = hiA;
    *(__nv_bfloat162*)(zhi + (size_t)node * HID + c + 2) = hiB;
    *(__nv_bfloat162*)(zlo + (size_t)node * HID + c)     = loA;
    *(__nv_bfloat162*)(zlo + (size_t)node * HID + c + 2) = loB;
}

// ---------------- elementwise / stats ----------------
__global__ void k_node_emb(const int* __restrict__ x, const float* __restrict__ W) {
    int i = blockIdx.x * blockDim.x + threadIdx.x;
    if (i >= NNODES * HID) return;
    int n = i >> 8, c = i & 255;
    g_h[i] = W[x[n] * HID + c];
}

__global__ void k_zero_cnt() { g_cnt[threadIdx.x] = 0; }
__global__ void k_count(const int* __restrict__ batch) {
    int i = blockIdx.x * blockDim.x + threadIdx.x;
    if (i < NNODES) atomicAdd(&g_cnt[batch[i]], 1);
}
__global__ void k_scan() {
    if (threadIdx.x == 0) {
        int acc = 0;
        for (int g = 0; g < NGRAPHS; g++) { g_start[g] = acc; acc += g_cnt[g]; }
    }
}

__global__ void k_stats(const float* __restrict__ alpha) {
    int g = blockIdx.x, c = threadIdx.x;
    int s = g_start[g], n = g_cnt[g];
    float sum = 0.f, sq = 0.f;
    #pragma unroll 4
    for (int i = 0; i < n; i++) {
        float v = g_h[(size_t)(s + i) * HID + c];
        sum += v; sq += v * v;
    }
    float inv = 1.f / (float)(n > 0 ? n : 1);
    float mu = sum * inv;
    float al = alpha[c];
    float var = sq * inv - (2.f * al - al * al) * mu * mu;
    g_mu[g * HID + c]    = mu;
    g_amean[g * HID + c] = al * mu;
    g_rstd[g * HID + c]  = rsqrtf(var + 1e-5f);
}

__global__ void k_poolnorm(const float* __restrict__ gamma, const float* __restrict__ beta) {
    int g = blockIdx.x, c = threadIdx.x;
    float mu = g_mu[g * HID + c];
    g_pool[g * HID + c] = gamma[c] * (mu - g_amean[g * HID + c]) * g_rstd[g * HID + c] + beta[c];
}

// ---------------- head ----------------
__global__ void k_cbio(const float* __restrict__ bio, const float* __restrict__ W1) {
    int j = threadIdx.x;
    float acc = 0.f;
    for (int k = 0; k < BIO; k++) acc += bio[k] * W1[(HID + k) * HID + j];
    g_cbio[j] = acc;
}

__global__ void k_head(const float* __restrict__ W1, const float* __restrict__ b1,
                       const float* __restrict__ W2, const float* __restrict__ b2,
                       float* __restrict__ out) {
    int g = blockIdx.x, j = threadIdx.x;
    __shared__ float sh[HID];
    __shared__ float red[HID];
    sh[j] = g_pool[g * HID + j];
    __syncthreads();
    float acc = b1[j] + g_cbio[j];
    for (int k = 0; k < HID; k++) acc += sh[k] * W1[k * HID + j];
    acc = fmaxf(acc, 0.f);
    red[j] = acc * W2[j];
    __syncthreads();
    for (int st = 128; st > 0; st >>= 1) {
        if (j < st) red[j] += red[j + st];
        __syncthreads();
    }
    if (j == 0) out[g] = red[0] + b2[0];
}

// ---------------- launch ----------------
extern "C" void kernel_launch(void* const* d_in, const int* in_sizes, int n_in,
                              void* d_out, int out_size) {
    const int*   x    = (const int*)d_in[0];
    const int*   ei   = (const int*)d_in[1];
    const float* ea   = (const float*)d_in[2];
    const int*   batch= (const int*)d_in[3];
    const float* nodeW= (const float*)d_in[4];
    const float* eW   = (const float*)d_in[5];
    const float* eb   = (const float*)d_in[6];
    const float* mW1  = (const float*)d_in[7];
    const float* mb1  = (const float*)d_in[8];
    const float* mW2  = (const float*)d_in[9];
    const float* mb2  = (const float*)d_in[10];
    const float* ss   = (const float*)d_in[11];
    const float* cW1  = (const float*)d_in[12];
    const float* cb1  = (const float*)d_in[13];
    const float* cW2  = (const float*)d_in[14];
    const float* cb2  = (const float*)d_in[15];
    const float* ceps = (const float*)d_in[16];
    const float* ng   = (const float*)d_in[17];
    const float* nb   = (const float*)d_in[18];
    const float* na   = (const float*)d_in[19];
    const float* bio  = (const float*)d_in[20];
    const float* hW1  = (const float*)d_in[21];
    const float* hb1  = (const float*)d_in[22];
    const float* hW2  = (const float*)d_in[23];
    const float* hb2  = (const float*)d_in[24];
    float* out = (float*)d_out;

    const int* src = ei;
    const int* dst = ei + NEDGES;

    void *pe, *pt, *ph, *pz, *pwh, *pwl;
    cudaGetSymbolAddress(&pe, g_e);
    cudaGetSymbolAddress(&pt, g_t);
    cudaGetSymbolAddress(&ph, g_h);
    cudaGetSymbolAddress(&pz, g_z);
    cudaGetSymbolAddress(&pwh, g_wt_hi);
    cudaGetSymbolAddress(&pwl, g_wt_lo);
    float* fe = (float*)pe;
    float* fh = (float*)ph;
    __nv_bfloat16* thi = (__nv_bfloat16*)pt;
    __nv_bfloat16* tlo = thi + (size_t)NEDGES * HID;
    __nv_bfloat16* zhi = (__nv_bfloat16*)pz;
    __nv_bfloat16* zlo = zhi + (size_t)NNODES * HID;
    __nv_bfloat16* wh = (__nv_bfloat16*)pwh;
    __nv_bfloat16* wl = (__nv_bfloat16*)pwl;

    cudaFuncSetAttribute(k_mgemm<0, 1, 1, 0, 0>, cudaFuncAttributeMaxDynamicSharedMemorySize, GSMEM);
    cudaFuncSetAttribute(k_mgemm<1, 0, 0, 1, 1>, cudaFuncAttributeMaxDynamicSharedMemorySize, GSMEM);
    cudaFuncSetAttribute(k_mgemm<0, 0, 0, 1, 0>, cudaFuncAttributeMaxDynamicSharedMemorySize, GSMEM);

    const int T = 256;
    int nodeElems = NNODES * HID;

    // 1: weight split (slots: 1=edgeW2, 2+l=convW1[l], 5+l=convW2[l]; slot0 unused)
    WPtrs wp;
    wp.p[0] = mW1; wp.p[1] = mW2;
    for (int l = 0; l < NLAYERS; l++) { wp.p[2 + l] = cW1 + l * HID * HID; wp.p[5 + l] = cW2 + l * HID * HID; }
    k_wsplit_all<<<dim3(HID, 8), HID>>>(wp);
    // 2: fold edge emb + W1
    k_wfold<<<1, HID>>>(eW, eb, mW1, mb1);
    // 3: zero CSR
    k_zero_nodes<<<(NNODES + T - 1) / T, T>>>();

    dim3 ge((NEDGES + 127) / 128, 2);
    dim3 gn((NNODES + 127) / 128, 2);

    // 4: fused edge MLP (single GEMM; A computed on the fly) — profiled launch
    k_mgemm<0, 1, 1, 0, 0><<<ge, 256, GSMEM>>>(nullptr, nullptr, nullptr,
                                               wh + 65536, wl + 65536, mb2,
                                               fe, nullptr, nullptr, NEDGES, ea, ss);

    // 5-9: CSR build
    k_deg<<<(NEDGES + T - 1) / T, T>>>(dst);
    k_scan_partial<<<NBLK, SBLK>>>();
    k_scan_blocks<<<1, 512>>>();
    k_scan_apply<<<NBLK, SBLK>>>();
    k_fill<<<(NEDGES + T - 1) / T, T>>>(dst);

    // node embedding; per-graph ranges
    k_node_emb<<<(nodeElems + T - 1) / T, T>>>(x, nodeW);
    k_zero_cnt<<<1, NGRAPHS>>>();
    k_count<<<(NNODES + T - 1) / T, T>>>(batch);
    k_scan<<<1, 32>>>();

    for (int l = 0; l < NLAYERS; l++) {
        if (l == 0)
            k_aggregate<0><<<(NNODES + 3) / 4, 256>>>(src, batch, ceps, l, nullptr, nullptr, zhi, zlo);
        else
            k_aggregate<1><<<(NNODES + 3) / 4, 256>>>(src, batch, ceps, l,
                                                      ng + (l - 1) * HID, nb + (l - 1) * HID, zhi, zlo);
        k_mgemm<1, 0, 0, 1, 1><<<gn, 256, GSMEM>>>(nullptr, zhi, zlo,
                                                   wh + (size_t)(2 + l) * 65536, wl + (size_t)(2 + l) * 65536,
                                                   cb1 + l * HID, nullptr, thi, tlo, NNODES,
                                                   nullptr, nullptr);
        k_mgemm<0, 0, 0, 1, 0><<<gn, 256, GSMEM>>>(nullptr, thi, tlo,
                                                   wh + (size_t)(5 + l) * 65536, wl + (size_t)(5 + l) * 65536,
                                                   cb2 + l * HID, fh, nullptr, nullptr, NNODES,
                                                   nullptr, nullptr);
        k_stats<<<NGRAPHS, HID>>>(na + l * HID);
    }

    // final pool via closed form + head
    k_poolnorm<<<NGRAPHS, HID>>>(ng + (NLAYERS - 1) * HID, nb + (NLAYERS - 1) * HID);
    k_cbio<<<1, HID>>>(bio, hW1);
    k_head<<<NGRAPHS, HID>>>(hW1, hb1, hW2, hb2, out);
}